// round 5
// baseline (speedup 1.0000x reference)
#include <cuda_runtime.h>
#include <cuda_bf16.h>
#include <math.h>
#include <stdint.h>
#include <stddef.h>

#define NB 2
#define NS 2048
#define NC 2048
#define ND 128
#define NH 16
#define NM (NB * NS)       // 4096
#define NBH (NB * NH)      // 32
#define RMS_EPS 1.1920928955078125e-07f
#define SM_SCALE 0.08838834764831844f

typedef __nv_bfloat16 bf16;

// ---------------- scratch (device globals; no allocation) ----------------
__device__ float g_q[(size_t)NM * NC];
__device__ float g_k[(size_t)NM * NC];
__device__ float g_v[(size_t)NM * NC];
__device__ float g_ctx[(size_t)NM * NC];
__device__ float g_sc[(size_t)NBH * NS * NS];          // 512 MB raw scores

// int8 two-level operands + per-row scales
__device__ int8_t g_x1[(size_t)NM * NC],  g_x2[(size_t)NM * NC];
__device__ int8_t g_wq1[(size_t)NC * NC], g_wq2[(size_t)NC * NC];
__device__ int8_t g_wk1[(size_t)NC * NC], g_wk2[(size_t)NC * NC];
__device__ int8_t g_wv1[(size_t)NC * NC], g_wv2[(size_t)NC * NC];
__device__ int8_t g_wo1[(size_t)NC * NC], g_wo2[(size_t)NC * NC];
__device__ int8_t g_q1[(size_t)NM * NC],  g_q2[(size_t)NM * NC];
__device__ int8_t g_k1[(size_t)NM * NC],  g_k2[(size_t)NM * NC];
__device__ int8_t g_c1[(size_t)NM * NC],  g_c2[(size_t)NM * NC];
__device__ float g_sx[NM], g_swq[NC], g_swk[NC], g_swv[NC], g_swo[NC];
__device__ float g_sq[NM * NH], g_sk[NM * NH], g_sctx[NM];

// bf16 split operands for PV (probs need floating-point relative precision)
__device__ bf16 g_vth[(size_t)NB * NC * NS], g_vtl[(size_t)NB * NC * NS];
__device__ bf16 g_ph[(size_t)NBH * NS * NS], g_pl[(size_t)NBH * NS * NS];

// ---------------- PTX helpers (sm_80-era, family-target safe) -------------
__device__ __forceinline__ uint32_t smem_to_u32(const void* p) {
    uint32_t a;
    asm("{ .reg .u64 t; cvta.to.shared.u64 t, %1; cvt.u32.u64 %0, t; }"
        : "=r"(a) : "l"(p));
    return a;
}
__device__ __forceinline__ void cp_async16(uint32_t dst, const void* src) {
    asm volatile("cp.async.cg.shared.global [%0], [%1], 16;"
                 :: "r"(dst), "l"(src) : "memory");
}
__device__ __forceinline__ void cp_commit() {
    asm volatile("cp.async.commit_group;" ::: "memory");
}
template <int N>
__device__ __forceinline__ void cp_wait() {
    asm volatile("cp.async.wait_group %0;" :: "n"(N) : "memory");
}
__device__ __forceinline__ void ldm_x4(uint32_t (&r)[4], uint32_t addr) {
    asm volatile("ldmatrix.sync.aligned.m8n8.x4.shared.b16 {%0,%1,%2,%3}, [%4];"
                 : "=r"(r[0]), "=r"(r[1]), "=r"(r[2]), "=r"(r[3]) : "r"(addr));
}
__device__ __forceinline__ void mma_bf16(float (&d)[4], const uint32_t (&a)[4],
                                         uint32_t b0, uint32_t b1) {
    asm volatile("mma.sync.aligned.m16n8k16.row.col.f32.bf16.bf16.f32 "
                 "{%0,%1,%2,%3}, {%4,%5,%6,%7}, {%8,%9}, {%0,%1,%2,%3};"
                 : "+f"(d[0]), "+f"(d[1]), "+f"(d[2]), "+f"(d[3])
                 : "r"(a[0]), "r"(a[1]), "r"(a[2]), "r"(a[3]), "r"(b0), "r"(b1));
}
__device__ __forceinline__ void mma_s8(int (&d)[4], const uint32_t (&a)[4],
                                       uint32_t b0, uint32_t b1) {
    asm volatile("mma.sync.aligned.m16n8k32.row.col.s32.s8.s8.s32 "
                 "{%0,%1,%2,%3}, {%4,%5,%6,%7}, {%8,%9}, {%0,%1,%2,%3};"
                 : "+r"(d[0]), "+r"(d[1]), "+r"(d[2]), "+r"(d[3])
                 : "r"(a[0]), "r"(a[1]), "r"(a[2]), "r"(a[3]), "r"(b0), "r"(b1));
}

__device__ __forceinline__ void split2(float x, bf16& h, bf16& l) {
    h = __float2bfloat16_rn(x);
    l = __float2bfloat16_rn(x - __bfloat162float(h));
}
// two-level int8 quant: x ~ s1*(a1 + a2/128), |a1|<=127, |a2|<=64
__device__ __forceinline__ void q2lvl(float x, float s1, float inv1,
                                      int8_t& c1, int8_t& c2) {
    float a1 = rintf(x * inv1);
    float r  = x - a1 * s1;
    float a2 = rintf(r * inv1 * 128.0f);
    c1 = (int8_t)(int)a1;
    c2 = (int8_t)(int)a2;
}

// =========================================================================
// int8 IMMA GEMM: 128x128 CTA tile, 512 threads, warp tile 16x64, K-chunk 64
// smem/stage: [A1|A2|B1|B2], each 128 rows x 80B (64B data + 16B pad)
// =========================================================================
#define IROW_BYTES 80
#define ITILE_BYTES (128 * IROW_BYTES)      // 10240
#define ISTAGE_BYTES (4 * ITILE_BYTES)      // 40960
#define IGEMM_SMEM (2 * ISTAGE_BYTES)       // 81920

__device__ __forceinline__ void load_tile_s8(uint32_t smbase, const int8_t* g,
                                             int ld, int k0, int tid) {
    int row = tid >> 2;                      // 0..127
    int c = tid & 3;                         // 16B chunk
    cp_async16(smbase + row * IROW_BYTES + c * 16,
               g + (size_t)row * ld + k0 + c * 16);
}

// Out[r,c] = sA[r*sAs]*sB[c*sBs]*(acc1 + acc2/128) (+ bias[c])
__device__ __forceinline__ void gemm_s8_tile(
    const int8_t* __restrict__ A1, const int8_t* __restrict__ A2, int lda,
    const int8_t* __restrict__ B1, const int8_t* __restrict__ B2, int ldb,
    const float* __restrict__ sA, int sAs,
    const float* __restrict__ sB, int sBs,
    const float* __restrict__ bias, float* __restrict__ Out, int ldo, int K)
{
    extern __shared__ char sm[];
    uint32_t sb = smem_to_u32(sm);
    const int tid = threadIdx.x;             // 512 threads = 16 warps
    const int lane = tid & 31;
    const int warp = tid >> 5;
    const int wm = warp >> 1;                // 0..7  rows: wm*16
    const int wn = warp & 1;                 // 0..1  cols: wn*64

    int acc1[8][4], acc2[8][4];
    #pragma unroll
    for (int nt = 0; nt < 8; nt++)
        #pragma unroll
        for (int j = 0; j < 4; j++) { acc1[nt][j] = 0; acc2[nt][j] = 0; }

    const int nch = K >> 6;

    auto load_chunk = [&](int ch, int s) {
        uint32_t base = sb + s * ISTAGE_BYTES;
        int k0 = ch << 6;
        load_tile_s8(base,                   A1, lda, k0, tid);
        load_tile_s8(base + ITILE_BYTES,     A2, lda, k0, tid);
        load_tile_s8(base + 2 * ITILE_BYTES, B1, ldb, k0, tid);
        load_tile_s8(base + 3 * ITILE_BYTES, B2, ldb, k0, tid);
    };

    load_chunk(0, 0);
    cp_commit();

    for (int ch = 0; ch < nch; ch++) {
        int cur = ch & 1;
        if (ch + 1 < nch) {
            load_chunk(ch + 1, cur ^ 1);
            cp_commit();
            cp_wait<1>();
        } else {
            cp_wait<0>();
        }
        __syncthreads();

        uint32_t base = sb + cur * ISTAGE_BYTES;
        #pragma unroll
        for (int ks = 0; ks < 2; ks++) {
            uint32_t koff = (uint32_t)(ks * 32 + (lane >> 4) * 16);
            uint32_t a1f[4], a2f[4];
            {
                uint32_t r = wm * 16 + (lane & 15);
                uint32_t addr = base + r * IROW_BYTES + koff;
                ldm_x4(a1f, addr);
                ldm_x4(a2f, addr + ITILE_BYTES);
            }
            uint32_t b1f[4][4], b2f[4][4];
            #pragma unroll
            for (int ng = 0; ng < 4; ng++) {
                uint32_t r = wn * 64 + ng * 16 + (lane & 15);
                uint32_t addr = base + 2 * ITILE_BYTES + r * IROW_BYTES + koff;
                ldm_x4(b1f[ng], addr);
                ldm_x4(b2f[ng], addr + ITILE_BYTES);
            }
            #pragma unroll
            for (int ng = 0; ng < 4; ng++) {
                mma_s8(acc1[2 * ng],     a1f, b1f[ng][0], b1f[ng][2]);
                mma_s8(acc1[2 * ng + 1], a1f, b1f[ng][1], b1f[ng][3]);
                mma_s8(acc2[2 * ng],     a1f, b2f[ng][0], b2f[ng][2]);
                mma_s8(acc2[2 * ng + 1], a1f, b2f[ng][1], b2f[ng][3]);
                mma_s8(acc2[2 * ng],     a2f, b1f[ng][0], b1f[ng][2]);
                mma_s8(acc2[2 * ng + 1], a2f, b1f[ng][1], b1f[ng][3]);
            }
        }
        __syncthreads();
    }

    // epilogue
    int r0 = wm * 16 + (lane >> 2);
    float sa0 = sA[(size_t)r0 * sAs];
    float sa1 = sA[(size_t)(r0 + 8) * sAs];
    #pragma unroll
    for (int nt = 0; nt < 8; nt++) {
        int c = wn * 64 + nt * 8 + (lane & 3) * 2;
        float sb0 = sB[(size_t)c * sBs];
        float sb1 = sB[(size_t)(c + 1) * sBs];
        float bx = 0.0f, by = 0.0f;
        if (bias) { bx = bias[c]; by = bias[c + 1]; }
        const float inv128 = 1.0f / 128.0f;
        float2 v0, v1;
        v0.x = ((float)acc1[nt][0] + (float)acc2[nt][0] * inv128) * sa0 * sb0 + bx;
        v0.y = ((float)acc1[nt][1] + (float)acc2[nt][1] * inv128) * sa0 * sb1 + by;
        v1.x = ((float)acc1[nt][2] + (float)acc2[nt][2] * inv128) * sa1 * sb0 + bx;
        v1.y = ((float)acc1[nt][3] + (float)acc2[nt][3] * inv128) * sa1 * sb1 + by;
        *(float2*)(Out + (size_t)r0 * ldo + c) = v0;
        *(float2*)(Out + (size_t)(r0 + 8) * ldo + c) = v1;
    }
}

// ---------------- int8 GEMM wrappers ----------------
__global__ __launch_bounds__(512)
void k_gemm_nt_s8(const int8_t* __restrict__ A1, const int8_t* __restrict__ A2,
                  const int8_t* __restrict__ B1, const int8_t* __restrict__ B2,
                  const float* __restrict__ sA, const float* __restrict__ sB,
                  const float* __restrict__ bias, float* __restrict__ Out)
{
    size_t bm = (size_t)blockIdx.y * 128;
    size_t bn = (size_t)blockIdx.x * 128;
    gemm_s8_tile(A1 + bm * NC, A2 + bm * NC, NC,
                 B1 + bn * NC, B2 + bn * NC, NC,
                 sA + bm, 1, sB + bn, 1,
                 bias + bn, Out + bm * NC + bn, NC, NC);
}

__global__ __launch_bounds__(512)
void k_gemm_scores_s8()
{
    int bh = blockIdx.z, b = bh >> 4, h = bh & 15;
    size_t bm = (size_t)blockIdx.y * 128;
    size_t bn = (size_t)blockIdx.x * 128;
    size_t arow = ((size_t)b * NS + bm) * NC + (size_t)h * ND;
    size_t brow = ((size_t)b * NS + bn) * NC + (size_t)h * ND;
    float* Out = g_sc + (size_t)bh * NS * NS + bm * NS + bn;
    gemm_s8_tile(g_q1 + arow, g_q2 + arow, NC,
                 g_k1 + brow, g_k2 + brow, NC,
                 g_sq + ((size_t)b * NS + bm) * NH + h, NH,
                 g_sk + ((size_t)b * NS + bn) * NH + h, NH,
                 nullptr, Out, NS, ND);
}

// =========================================================================
// bf16x3 HMMA GEMM (for PV only): 128x128 tile, 256 threads, K-chunk 32
// =========================================================================
#define KCH 32
#define ROW_BYTES 80
#define TILE_BYTES (128 * ROW_BYTES)        // 10240
#define STAGE_BYTES (4 * TILE_BYTES)        // 40960
#define GEMM_SMEM (2 * STAGE_BYTES)         // 81920

__device__ __forceinline__ void load_tile_async(uint32_t smbase, const bf16* g,
                                                int ld, int k0, int tid) {
    const char* gp = (const char*)(g + k0);
    #pragma unroll
    for (int j = 0; j < 2; j++) {
        int i = tid + j * 256;
        int row = i >> 2;
        int c = i & 3;
        cp_async16(smbase + row * ROW_BYTES + c * 16,
                   gp + (size_t)row * ld * 2 + c * 16);
    }
}

__device__ __forceinline__ void gemm_hmma_tile(
    const bf16* __restrict__ Ah, const bf16* __restrict__ Al, int lda,
    const bf16* __restrict__ Bh, const bf16* __restrict__ Bl, int ldb,
    float* __restrict__ Out, int ldo, int K)
{
    extern __shared__ char sm[];
    uint32_t sb = smem_to_u32(sm);
    const int tid = threadIdx.x;            // 256 threads = 8 warps
    const int lane = tid & 31;
    const int warp = tid >> 5;
    const int wm = warp >> 1;
    const int wn = warp & 1;

    float acc[2][8][4];
    #pragma unroll
    for (int mt = 0; mt < 2; mt++)
        #pragma unroll
        for (int nt = 0; nt < 8; nt++)
            #pragma unroll
            for (int j = 0; j < 4; j++) acc[mt][nt][j] = 0.0f;

    const int nch = K / KCH;

    auto load_chunk = [&](int ch, int s) {
        uint32_t base = sb + s * STAGE_BYTES;
        int k0 = ch * KCH;
        load_tile_async(base,                  Ah, lda, k0, tid);
        load_tile_async(base + TILE_BYTES,     Al, lda, k0, tid);
        load_tile_async(base + 2 * TILE_BYTES, Bh, ldb, k0, tid);
        load_tile_async(base + 3 * TILE_BYTES, Bl, ldb, k0, tid);
    };

    load_chunk(0, 0);
    cp_commit();

    for (int ch = 0; ch < nch; ch++) {
        int cur = ch & 1;
        if (ch + 1 < nch) {
            load_chunk(ch + 1, cur ^ 1);
            cp_commit();
            cp_wait<1>();
        } else {
            cp_wait<0>();
        }
        __syncthreads();

        uint32_t base = sb + cur * STAGE_BYTES;
        #pragma unroll
        for (int ks = 0; ks < 2; ks++) {
            uint32_t koff = (uint32_t)(ks * 32 + (lane >> 4) * 16);
            uint32_t ah[2][4], al[2][4];
            #pragma unroll
            for (int mt = 0; mt < 2; mt++) {
                uint32_t r = wm * 32 + mt * 16 + (lane & 15);
                uint32_t addr = base + r * ROW_BYTES + koff;
                ldm_x4(ah[mt], addr);
                ldm_x4(al[mt], addr + TILE_BYTES);
            }
            uint32_t bh[4][4], bl[4][4];
            #pragma unroll
            for (int ng = 0; ng < 4; ng++) {
                uint32_t r = wn * 64 + ng * 16 + (lane & 15);
                uint32_t addr = base + 2 * TILE_BYTES + r * ROW_BYTES + koff;
                ldm_x4(bh[ng], addr);
                ldm_x4(bl[ng], addr + TILE_BYTES);
            }
            #pragma unroll
            for (int mt = 0; mt < 2; mt++)
                #pragma unroll
                for (int ng = 0; ng < 4; ng++) {
                    mma_bf16(acc[mt][2 * ng],     ah[mt], bh[ng][0], bh[ng][2]);
                    mma_bf16(acc[mt][2 * ng],     ah[mt], bl[ng][0], bl[ng][2]);
                    mma_bf16(acc[mt][2 * ng],     al[mt], bh[ng][0], bh[ng][2]);
                    mma_bf16(acc[mt][2 * ng + 1], ah[mt], bh[ng][1], bh[ng][3]);
                    mma_bf16(acc[mt][2 * ng + 1], ah[mt], bl[ng][1], bl[ng][3]);
                    mma_bf16(acc[mt][2 * ng + 1], al[mt], bh[ng][1], bh[ng][3]);
                }
        }
        __syncthreads();
    }

    #pragma unroll
    for (int mt = 0; mt < 2; mt++) {
        int r0 = wm * 32 + mt * 16 + (lane >> 2);
        #pragma unroll
        for (int nt = 0; nt < 8; nt++) {
            int c = wn * 64 + nt * 8 + (lane & 3) * 2;
            float2 v0 = { acc[mt][nt][0], acc[mt][nt][1] };
            float2 v1 = { acc[mt][nt][2], acc[mt][nt][3] };
            *(float2*)(Out + (size_t)r0 * ldo + c) = v0;
            *(float2*)(Out + (size_t)(r0 + 8) * ldo + c) = v1;
        }
    }
}

// PV: per (b,h): ctx_h[2048,128] = P @ V_h (V^T layout -> NT), fp32 out
__global__ __launch_bounds__(256)
void k_gemm_pv()
{
    int bh = blockIdx.z, b = bh >> 4, h = bh & 15;
    size_t bm = (size_t)blockIdx.y * 128;
    size_t arow = (size_t)bh * NS * NS + bm * NS;
    size_t brow = ((size_t)b * NC + (size_t)h * ND) * NS;
    size_t orow = ((size_t)b * NS + bm) * NC + (size_t)h * ND;
    gemm_hmma_tile(g_ph + arow, g_pl + arow, NS,
                   g_vth + brow, g_vtl + brow, NS,
                   g_ctx + orow, NC, NS);
}

// ---------------- elementwise kernels ----------------
// per-row two-level int8 quantization (rows of length NC=2048)
__global__ __launch_bounds__(256) void quant_rows(const float* __restrict__ src,
                                                  int8_t* __restrict__ d1,
                                                  int8_t* __restrict__ d2,
                                                  float* __restrict__ scl)
{
    const float* row = src + (size_t)blockIdx.x * NC;
    int tid = threadIdx.x;
    __shared__ float sh[8];

    float4 v0 = ((const float4*)row)[tid];
    float4 v1 = ((const float4*)row)[tid + 256];
    float mx = fmaxf(fmaxf(fmaxf(fabsf(v0.x), fabsf(v0.y)),
                           fmaxf(fabsf(v0.z), fabsf(v0.w))),
                     fmaxf(fmaxf(fabsf(v1.x), fabsf(v1.y)),
                           fmaxf(fabsf(v1.z), fabsf(v1.w))));
    #pragma unroll
    for (int o = 16; o; o >>= 1) mx = fmaxf(mx, __shfl_xor_sync(0xffffffffu, mx, o));
    if ((tid & 31) == 0) sh[tid >> 5] = mx;
    __syncthreads();
    if (tid < 32) {
        float t = sh[tid & 7];
        #pragma unroll
        for (int o = 4; o; o >>= 1) t = fmaxf(t, __shfl_xor_sync(0xffffffffu, t, o));
        if (tid == 0) sh[0] = t;
    }
    __syncthreads();
    mx = sh[0];

    float s1 = (mx > 0.0f) ? mx * (1.0f / 127.0f) : 1.0f;
    float inv1 = 1.0f / s1;
    if (tid == 0) scl[blockIdx.x] = s1;

    int8_t a[8], b[8];
    q2lvl(v0.x, s1, inv1, a[0], b[0]); q2lvl(v0.y, s1, inv1, a[1], b[1]);
    q2lvl(v0.z, s1, inv1, a[2], b[2]); q2lvl(v0.w, s1, inv1, a[3], b[3]);
    q2lvl(v1.x, s1, inv1, a[4], b[4]); q2lvl(v1.y, s1, inv1, a[5], b[5]);
    q2lvl(v1.z, s1, inv1, a[6], b[6]); q2lvl(v1.w, s1, inv1, a[7], b[7]);

    size_t base = (size_t)blockIdx.x * NC;
    *(char4*)(d1 + base + tid * 4)         = make_char4(a[0], a[1], a[2], a[3]);
    *(char4*)(d1 + base + (tid + 256) * 4) = make_char4(a[4], a[5], a[6], a[7]);
    *(char4*)(d2 + base + tid * 4)         = make_char4(b[0], b[1], b[2], b[3]);
    *(char4*)(d2 + base + (tid + 256) * 4) = make_char4(b[4], b[5], b[6], b[7]);
}

// V transpose + split to bf16 hi/lo (PV operand)
__global__ __launch_bounds__(256) void transpose_split_v()
{
    __shared__ float t[32][33];
    int b = blockIdx.z;
    int s0 = blockIdx.x * 32, c0 = blockIdx.y * 32;
    int tx = threadIdx.x, ty = threadIdx.y;  // 32 x 8
    #pragma unroll
    for (int j = 0; j < 4; j++) {
        int s = s0 + ty + j * 8;
        t[ty + j * 8][tx] = g_v[((size_t)b * NS + s) * NC + c0 + tx];
    }
    __syncthreads();
    #pragma unroll
    for (int j = 0; j < 4; j++) {
        int c = c0 + ty + j * 8;
        float v = t[tx][ty + j * 8];
        bf16 h, l;
        split2(v, h, l);
        size_t o = ((size_t)b * NC + c) * NS + s0 + tx;
        g_vth[o] = h;
        g_vtl[o] = l;
    }
}

// Per-head RMSNorm + RoPE; reads fp32 g_q/g_k, writes two-level int8 + scales
__global__ __launch_bounds__(256) void rmsnorm_rope(
    const float* __restrict__ rope,
    const float* __restrict__ gq, const float* __restrict__ gk)
{
    int warp = blockIdx.x * 8 + (threadIdx.x >> 5);
    int lane = threadIdx.x & 31;
    int m = warp >> 4;
    int h = warp & 15;
    int s = m & (NS - 1);

    size_t off = (size_t)m * NC + h * ND;
    const float* qr = g_q + off;
    const float* kr = g_k + off;
    const float* rp = rope + (size_t)s * (ND / 2) * 4;
    int d = lane * 4;

    float4 xq = *(const float4*)(qr + d);
    float4 xk = *(const float4*)(kr + d);
    float ssq = xq.x * xq.x + xq.y * xq.y + xq.z * xq.z + xq.w * xq.w;
    float ssk = xk.x * xk.x + xk.y * xk.y + xk.z * xk.z + xk.w * xk.w;
    #pragma unroll
    for (int o = 16; o; o >>= 1) {
        ssq += __shfl_xor_sync(0xffffffffu, ssq, o);
        ssk += __shfl_xor_sync(0xffffffffu, ssk, o);
    }
    float rq = rsqrtf(ssq * (1.0f / ND) + RMS_EPS);
    float rk = rsqrtf(ssk * (1.0f / ND) + RMS_EPS);

    float4 gqv = *(const float4*)(gq + d);
    float4 gkv = *(const float4*)(gk + d);
    xq.x *= rq * gqv.x; xq.y *= rq * gqv.y; xq.z *= rq * gqv.z; xq.w *= rq * gqv.w;
    xk.x *= rk * gkv.x; xk.y *= rk * gkv.y; xk.z *= rk * gkv.z; xk.w *= rk * gkv.w;

    float4 r0 = *(const float4*)(rp + (size_t)(2 * lane) * 4);
    float4 r1 = *(const float4*)(rp + (size_t)(2 * lane + 1) * 4);
    float4 oq, ok;
    oq.x = r0.x * xq.x + r0.y * xq.y;  oq.y = r0.z * xq.x + r0.w * xq.y;
    oq.z = r1.x * xq.z + r1.y * xq.w;  oq.w = r1.z * xq.z + r1.w * xq.w;
    ok.x = r0.x * xk.x + r0.y * xk.y;  ok.y = r0.z * xk.x + r0.w * xk.y;
    ok.z = r1.x * xk.z + r1.y * xk.w;  ok.w = r1.z * xk.z + r1.w * xk.w;

    // per-(m,h) segment max over 128 elems
    float mq = fmaxf(fmaxf(fabsf(oq.x), fabsf(oq.y)), fmaxf(fabsf(oq.z), fabsf(oq.w)));
    float mk = fmaxf(fmaxf(fabsf(ok.x), fabsf(ok.y)), fmaxf(fabsf(ok.z), fabsf(ok.w)));
    #pragma unroll
    for (int o = 16; o; o >>= 1) {
        mq = fmaxf(mq, __shfl_xor_sync(0xffffffffu, mq, o));
        mk = fmaxf(mk, __shfl_xor_sync(0xffffffffu, mk, o));
    }
    float s1q = (mq > 0.0f) ? mq * (1.0f / 127.0f) : 1.0f;
    float s1k = (mk > 0.0f) ? mk * (1.0f / 127.0f) : 1.0f;
    float iq = 1.0f / s1q, ik = 1.0f / s1k;
    if (lane == 0) {
        g_sq[(size_t)m * NH + h] = s1q;
        g_sk[(size_t)m * NH + h] = s1k;
    }

    int8_t a[4], b2[4];
    q2lvl(oq.x, s1q, iq, a[0], b2[0]); q2lvl(oq.y, s1q, iq, a[1], b2[1]);
    q2lvl(oq.z, s1q, iq, a[2], b2[2]); q2lvl(oq.w, s1q, iq, a[3], b2[3]);
    *(char4*)(g_q1 + off + d) = make_char4(a[0], a[1], a[2], a[3]);
    *(char4*)(g_q2 + off + d) = make_char4(b2[0], b2[1], b2[2], b2[3]);

    q2lvl(ok.x, s1k, ik, a[0], b2[0]); q2lvl(ok.y, s1k, ik, a[1], b2[1]);
    q2lvl(ok.z, s1k, ik, a[2], b2[2]); q2lvl(ok.w, s1k, ik, a[3], b2[3]);
    *(char4*)(g_k1 + off + d) = make_char4(a[0], a[1], a[2], a[3]);
    *(char4*)(g_k2 + off + d) = make_char4(b2[0], b2[1], b2[2], b2[3]);
}

// Row softmax over 2048 keys; reads fp32 scores, writes split bf16 probs.
__global__ __launch_bounds__(256) void softmax_rows()
{
    const float* p = g_sc + (size_t)blockIdx.x * NS;
    bf16* ph = g_ph + (size_t)blockIdx.x * NS;
    bf16* pl = g_pl + (size_t)blockIdx.x * NS;
    int tid = threadIdx.x;
    __shared__ float sh[8];

    float4 v0 = ((const float4*)p)[tid];
    float4 v1 = ((const float4*)p)[tid + 256];
    float mx = fmaxf(fmaxf(fmaxf(v0.x, v0.y), fmaxf(v0.z, v0.w)),
                     fmaxf(fmaxf(v1.x, v1.y), fmaxf(v1.z, v1.w)));
    #pragma unroll
    for (int o = 16; o; o >>= 1) mx = fmaxf(mx, __shfl_xor_sync(0xffffffffu, mx, o));
    if ((tid & 31) == 0) sh[tid >> 5] = mx;
    __syncthreads();
    if (tid < 32) {
        float t = sh[tid & 7];
        #pragma unroll
        for (int o = 4; o; o >>= 1) t = fmaxf(t, __shfl_xor_sync(0xffffffffu, t, o));
        if (tid == 0) sh[0] = t;
    }
    __syncthreads();
    mx = sh[0];
    __syncthreads();

    v0.x = __expf((v0.x - mx) * SM_SCALE); v0.y = __expf((v0.y - mx) * SM_SCALE);
    v0.z = __expf((v0.z - mx) * SM_SCALE); v0.w = __expf((v0.w - mx) * SM_SCALE);
    v1.x = __expf((v1.x - mx) * SM_SCALE); v1.y = __expf((v1.y - mx) * SM_SCALE);
    v1.z = __expf((v1.z - mx) * SM_SCALE); v1.w = __expf((v1.w - mx) * SM_SCALE);
    float sum = v0.x + v0.y + v0.z + v0.w + v1.x + v1.y + v1.z + v1.w;
    #pragma unroll
    for (int o = 16; o; o >>= 1) sum += __shfl_xor_sync(0xffffffffu, sum, o);
    if ((tid & 31) == 0) sh[tid >> 5] = sum;
    __syncthreads();
    if (tid < 32) {
        float t = sh[tid & 7];
        #pragma unroll
        for (int o = 4; o; o >>= 1) t += __shfl_xor_sync(0xffffffffu, t, o);
        if (tid == 0) sh[0] = t;
    }
    __syncthreads();
    float inv = 1.0f / sh[0];
    v0.x *= inv; v0.y *= inv; v0.z *= inv; v0.w *= inv;
    v1.x *= inv; v1.y *= inv; v1.z *= inv; v1.w *= inv;

    bf16 h0, h1, h2, h3, l0, l1, l2, l3;
    split2(v0.x, h0, l0); split2(v0.y, h1, l1);
    split2(v0.z, h2, l2); split2(v0.w, h3, l3);
    *(__nv_bfloat162*)(ph + tid * 4)     = __nv_bfloat162{h0, h1};
    *(__nv_bfloat162*)(ph + tid * 4 + 2) = __nv_bfloat162{h2, h3};
    *(__nv_bfloat162*)(pl + tid * 4)     = __nv_bfloat162{l0, l1};
    *(__nv_bfloat162*)(pl + tid * 4 + 2) = __nv_bfloat162{l2, l3};

    split2(v1.x, h0, l0); split2(v1.y, h1, l1);
    split2(v1.z, h2, l2); split2(v1.w, h3, l3);
    *(__nv_bfloat162*)(ph + (tid + 256) * 4)     = __nv_bfloat162{h0, h1};
    *(__nv_bfloat162*)(ph + (tid + 256) * 4 + 2) = __nv_bfloat162{h2, h3};
    *(__nv_bfloat162*)(pl + (tid + 256) * 4)     = __nv_bfloat162{l0, l1};
    *(__nv_bfloat162*)(pl + (tid + 256) * 4 + 2) = __nv_bfloat162{l2, l3};
}

// ---------------- launch ----------------
extern "C" void kernel_launch(void* const* d_in, const int* in_sizes, int n_in,
                              void* d_out, int out_size)
{
    const float* x    = (const float*)d_in[0];
    const float* rope = (const float*)d_in[1];
    const float* Wq   = (const float*)d_in[2];
    const float* bq   = (const float*)d_in[3];
    const float* Wk   = (const float*)d_in[4];
    const float* bk   = (const float*)d_in[5];
    const float* Wv   = (const float*)d_in[6];
    const float* bv   = (const float*)d_in[7];
    const float* gq   = (const float*)d_in[8];
    const float* gk   = (const float*)d_in[9];
    const float* Wo   = (const float*)d_in[10];
    const float* bo   = (const float*)d_in[11];
    float* out = (float*)d_out;

    cudaFuncSetAttribute(k_gemm_nt_s8, cudaFuncAttributeMaxDynamicSharedMemorySize, IGEMM_SMEM);
    cudaFuncSetAttribute(k_gemm_scores_s8, cudaFuncAttributeMaxDynamicSharedMemorySize, IGEMM_SMEM);
    cudaFuncSetAttribute(k_gemm_pv, cudaFuncAttributeMaxDynamicSharedMemorySize, GEMM_SMEM);

    float *qp, *kp, *vp, *ctxp;
    int8_t *x1, *x2, *wq1, *wq2, *wk1, *wk2, *wv1, *wv2, *wo1, *wo2, *c1, *c2;
    float *sx, *swq, *swk, *swv, *swo, *sctx;
    cudaGetSymbolAddress((void**)&qp, g_q);
    cudaGetSymbolAddress((void**)&kp, g_k);
    cudaGetSymbolAddress((void**)&vp, g_v);
    cudaGetSymbolAddress((void**)&ctxp, g_ctx);
    cudaGetSymbolAddress((void**)&x1, g_x1);   cudaGetSymbolAddress((void**)&x2, g_x2);
    cudaGetSymbolAddress((void**)&wq1, g_wq1); cudaGetSymbolAddress((void**)&wq2, g_wq2);
    cudaGetSymbolAddress((void**)&wk1, g_wk1); cudaGetSymbolAddress((void**)&wk2, g_wk2);
    cudaGetSymbolAddress((void**)&wv1, g_wv1); cudaGetSymbolAddress((void**)&wv2, g_wv2);
    cudaGetSymbolAddress((void**)&wo1, g_wo1); cudaGetSymbolAddress((void**)&wo2, g_wo2);
    cudaGetSymbolAddress((void**)&c1, g_c1);   cudaGetSymbolAddress((void**)&c2, g_c2);
    cudaGetSymbolAddress((void**)&sx, g_sx);
    cudaGetSymbolAddress((void**)&swq, g_swq); cudaGetSymbolAddress((void**)&swk, g_swk);
    cudaGetSymbolAddress((void**)&swv, g_swv); cudaGetSymbolAddress((void**)&swo, g_swo);
    cudaGetSymbolAddress((void**)&sctx, g_sctx);

    // quantize inputs + weights
    quant_rows<<<NM, 256>>>(x, x1, x2, sx);
    quant_rows<<<NC, 256>>>(Wq, wq1, wq2, swq);
    quant_rows<<<NC, 256>>>(Wk, wk1, wk2, swk);
    quant_rows<<<NC, 256>>>(Wv, wv1, wv2, swv);
    quant_rows<<<NC, 256>>>(Wo, wo1, wo2, swo);

    dim3 gProj(NC / 128, NM / 128);          // (16, 32)
    k_gemm_nt_s8<<<gProj, 512, IGEMM_SMEM>>>(x1, x2, wq1, wq2, sx, swq, bq, qp);
    k_gemm_nt_s8<<<gProj, 512, IGEMM_SMEM>>>(x1, x2, wk1, wk2, sx, swk, bk, kp);
    k_gemm_nt_s8<<<gProj, 512, IGEMM_SMEM>>>(x1, x2, wv1, wv2, sx, swv, bv, vp);

    rmsnorm_rope<<<(NM * NH) / 8, 256>>>(rope, gq, gk);
    transpose_split_v<<<dim3(NS / 32, NC / 32, NB), dim3(32, 8)>>>();

    k_gemm_scores_s8<<<dim3(NS / 128, NS / 128, NBH), 512, IGEMM_SMEM>>>();
    softmax_rows<<<NBH * NS, 256>>>();
    k_gemm_pv<<<dim3(1, NS / 128, NBH), 256, GEMM_SMEM>>>();

    quant_rows<<<NM, 256>>>(ctxp, c1, c2, sctx);
    k_gemm_nt_s8<<<gProj, 512, IGEMM_SMEM>>>(c1, c2, wo1, wo2, sctx, swo, bo, out);
}

// round 6
// speedup vs baseline: 2.2365x; 2.2365x over previous
#include <cuda_runtime.h>
#include <cuda_bf16.h>
#include <math.h>
#include <stdint.h>
#include <stddef.h>

#define NB 2
#define NS 2048
#define NC 2048
#define ND 128
#define NH 16
#define NM (NB * NS)       // 4096
#define NBH (NB * NH)      // 32
#define RMS_EPS 1.1920928955078125e-07f
#define SM_SCALE 0.08838834764831844f

typedef __nv_bfloat16 bf16;

// ---------------- scratch (device globals; no allocation) ----------------
__device__ float g_q[(size_t)NM * NC];
__device__ float g_k[(size_t)NM * NC];
__device__ float g_v[(size_t)NM * NC];

__device__ bf16 g_xh[(size_t)NM * NC],  g_xl[(size_t)NM * NC];
__device__ bf16 g_wqh[(size_t)NC * NC], g_wql[(size_t)NC * NC];
__device__ bf16 g_wkh[(size_t)NC * NC], g_wkl[(size_t)NC * NC];
__device__ bf16 g_wvh[(size_t)NC * NC], g_wvl[(size_t)NC * NC];
__device__ bf16 g_woh[(size_t)NC * NC], g_wol[(size_t)NC * NC];
__device__ bf16 g_qh[(size_t)NM * NC],  g_ql[(size_t)NM * NC];
__device__ bf16 g_kh[(size_t)NM * NC],  g_kl[(size_t)NM * NC];
__device__ bf16 g_vth[(size_t)NB * NC * NS], g_vtl[(size_t)NB * NC * NS];
__device__ bf16 g_ch[(size_t)NM * NC],  g_cl[(size_t)NM * NC];

// ---------------- PTX helpers (sm_80-era, family-target safe) -------------
__device__ __forceinline__ uint32_t smem_to_u32(const void* p) {
    uint32_t a;
    asm("{ .reg .u64 t; cvta.to.shared.u64 t, %1; cvt.u32.u64 %0, t; }"
        : "=r"(a) : "l"(p));
    return a;
}
__device__ __forceinline__ void cp_async16(uint32_t dst, const void* src) {
    asm volatile("cp.async.cg.shared.global [%0], [%1], 16;"
                 :: "r"(dst), "l"(src) : "memory");
}
__device__ __forceinline__ void cp_commit() {
    asm volatile("cp.async.commit_group;" ::: "memory");
}
template <int N>
__device__ __forceinline__ void cp_wait() {
    asm volatile("cp.async.wait_group %0;" :: "n"(N) : "memory");
}
__device__ __forceinline__ void ldm_x4(uint32_t (&r)[4], uint32_t addr) {
    asm volatile("ldmatrix.sync.aligned.m8n8.x4.shared.b16 {%0,%1,%2,%3}, [%4];"
                 : "=r"(r[0]), "=r"(r[1]), "=r"(r[2]), "=r"(r[3]) : "r"(addr));
}
__device__ __forceinline__ void mma_bf16(float (&d)[4], const uint32_t (&a)[4],
                                         uint32_t b0, uint32_t b1) {
    asm volatile("mma.sync.aligned.m16n8k16.row.col.f32.bf16.bf16.f32 "
                 "{%0,%1,%2,%3}, {%4,%5,%6,%7}, {%8,%9}, {%0,%1,%2,%3};"
                 : "+f"(d[0]), "+f"(d[1]), "+f"(d[2]), "+f"(d[3])
                 : "r"(a[0]), "r"(a[1]), "r"(a[2]), "r"(a[3]), "r"(b0), "r"(b1));
}

__device__ __forceinline__ void split2(float x, bf16& h, bf16& l) {
    h = __float2bfloat16_rn(x);
    l = __float2bfloat16_rn(x - __bfloat162float(h));
}
// pack two floats into bf16x2 hi-part and lo-residual-part registers
__device__ __forceinline__ void pack_hl(float x, float y, uint32_t& hi, uint32_t& lo) {
    bf16 hx, lx, hy, ly;
    split2(x, hx, lx);
    split2(y, hy, ly);
    __nv_bfloat162 H{hx, hy}, L{lx, ly};
    hi = *reinterpret_cast<uint32_t*>(&H);
    lo = *reinterpret_cast<uint32_t*>(&L);
}

// =========================================================================
// bf16x3 HMMA GEMM (projections + out-proj): 128x128 tile, 256 thr, Kch 32
// =========================================================================
#define KCH 32
#define ROW_BYTES 80
#define TILE_BYTES (128 * ROW_BYTES)        // 10240
#define STAGE_BYTES (4 * TILE_BYTES)        // 40960
#define GEMM_SMEM (2 * STAGE_BYTES)         // 81920

__device__ __forceinline__ void load_tile_async(uint32_t smbase, const bf16* g,
                                                int ld, int k0, int tid) {
    const char* gp = (const char*)(g + k0);
    #pragma unroll
    for (int j = 0; j < 2; j++) {
        int i = tid + j * 256;
        int row = i >> 2;
        int c = i & 3;
        cp_async16(smbase + row * ROW_BYTES + c * 16,
                   gp + (size_t)row * ld * 2 + c * 16);
    }
}

__device__ __forceinline__ void gemm_hmma_tile(
    const bf16* __restrict__ Ah, const bf16* __restrict__ Al, int lda,
    const bf16* __restrict__ Bh, const bf16* __restrict__ Bl, int ldb,
    const float* __restrict__ bias, float* __restrict__ Out, int ldo, int K)
{
    extern __shared__ char sm[];
    uint32_t sb = smem_to_u32(sm);
    const int tid = threadIdx.x;            // 256 threads = 8 warps
    const int lane = tid & 31;
    const int warp = tid >> 5;
    const int wm = warp >> 1;
    const int wn = warp & 1;

    float acc[2][8][4];
    #pragma unroll
    for (int mt = 0; mt < 2; mt++)
        #pragma unroll
        for (int nt = 0; nt < 8; nt++)
            #pragma unroll
            for (int j = 0; j < 4; j++) acc[mt][nt][j] = 0.0f;

    const int nch = K / KCH;

    auto load_chunk = [&](int ch, int s) {
        uint32_t base = sb + s * STAGE_BYTES;
        int k0 = ch * KCH;
        load_tile_async(base,                  Ah, lda, k0, tid);
        load_tile_async(base + TILE_BYTES,     Al, lda, k0, tid);
        load_tile_async(base + 2 * TILE_BYTES, Bh, ldb, k0, tid);
        load_tile_async(base + 3 * TILE_BYTES, Bl, ldb, k0, tid);
    };

    load_chunk(0, 0);
    cp_commit();

    for (int ch = 0; ch < nch; ch++) {
        int cur = ch & 1;
        if (ch + 1 < nch) {
            load_chunk(ch + 1, cur ^ 1);
            cp_commit();
            cp_wait<1>();
        } else {
            cp_wait<0>();
        }
        __syncthreads();

        uint32_t base = sb + cur * STAGE_BYTES;
        #pragma unroll
        for (int ks = 0; ks < 2; ks++) {
            uint32_t koff = (uint32_t)(ks * 32 + (lane >> 4) * 16);
            uint32_t ah[2][4], al[2][4];
            #pragma unroll
            for (int mt = 0; mt < 2; mt++) {
                uint32_t r = wm * 32 + mt * 16 + (lane & 15);
                uint32_t addr = base + r * ROW_BYTES + koff;
                ldm_x4(ah[mt], addr);
                ldm_x4(al[mt], addr + TILE_BYTES);
            }
            uint32_t bh[4][4], bl[4][4];
            #pragma unroll
            for (int ng = 0; ng < 4; ng++) {
                uint32_t r = wn * 64 + ng * 16 + (lane & 15);
                uint32_t addr = base + 2 * TILE_BYTES + r * ROW_BYTES + koff;
                ldm_x4(bh[ng], addr);
                ldm_x4(bl[ng], addr + TILE_BYTES);
            }
            #pragma unroll
            for (int mt = 0; mt < 2; mt++)
                #pragma unroll
                for (int ng = 0; ng < 4; ng++) {
                    mma_bf16(acc[mt][2 * ng],     ah[mt], bh[ng][0], bh[ng][2]);
                    mma_bf16(acc[mt][2 * ng],     ah[mt], bl[ng][0], bl[ng][2]);
                    mma_bf16(acc[mt][2 * ng],     al[mt], bh[ng][0], bh[ng][2]);
                    mma_bf16(acc[mt][2 * ng + 1], ah[mt], bh[ng][1], bh[ng][3]);
                    mma_bf16(acc[mt][2 * ng + 1], ah[mt], bl[ng][1], bl[ng][3]);
                    mma_bf16(acc[mt][2 * ng + 1], al[mt], bh[ng][1], bh[ng][3]);
                }
        }
        __syncthreads();
    }

    #pragma unroll
    for (int mt = 0; mt < 2; mt++) {
        int r0 = wm * 32 + mt * 16 + (lane >> 2);
        #pragma unroll
        for (int nt = 0; nt < 8; nt++) {
            int c = wn * 64 + nt * 8 + (lane & 3) * 2;
            float bx = bias ? bias[c] : 0.0f;
            float by = bias ? bias[c + 1] : 0.0f;
            float2 v0 = { acc[mt][nt][0] + bx, acc[mt][nt][1] + by };
            float2 v1 = { acc[mt][nt][2] + bx, acc[mt][nt][3] + by };
            *(float2*)(Out + (size_t)r0 * ldo + c) = v0;
            *(float2*)(Out + (size_t)(r0 + 8) * ldo + c) = v1;
        }
    }
}

__global__ __launch_bounds__(256)
void k_gemm_nt(const bf16* __restrict__ Ah, const bf16* __restrict__ Al,
               const bf16* __restrict__ Bh, const bf16* __restrict__ Bl,
               const float* __restrict__ bias, float* __restrict__ Out)
{
    size_t bm = (size_t)blockIdx.y * 128;
    size_t bn = (size_t)blockIdx.x * 128;
    gemm_hmma_tile(Ah + bm * NC, Al + bm * NC, NC,
                   Bh + bn * NC, Bl + bn * NC, NC,
                   bias + bn, Out + bm * NC + bn, NC, NC);
}

// =========================================================================
// Flash attention: scores + online softmax + PV fused, bf16x3 throughout
// =========================================================================
#define FT_ROWB 272                          // 256B row + 16B pad
#define FT_TILE (128 * FT_ROWB)              // 34816
#define OFF_KH 0
#define OFF_KL FT_TILE
#define OFF_VH (2 * FT_TILE)
#define OFF_VL (3 * FT_TILE)
#define FLASH_SMEM (4 * FT_TILE)             // 139264

// Load a 128-row x 256B tile pair (hi/lo) into smem via cp.async (no commit).
__device__ __forceinline__ void fa_load_tile(uint32_t dsthi, uint32_t dstlo,
                                             const bf16* gh, const bf16* gl,
                                             size_t rowbase, size_t ldrow, int tid)
{
    #pragma unroll
    for (int i = 0; i < 8; i++) {
        int idx = tid + i * 256;
        int row = idx >> 4;
        int ch = idx & 15;
        const char* ph = (const char*)(gh + rowbase + (size_t)row * ldrow) + ch * 16;
        const char* pl = (const char*)(gl + rowbase + (size_t)row * ldrow) + ch * 16;
        cp_async16(dsthi + row * FT_ROWB + ch * 16, ph);
        cp_async16(dstlo + row * FT_ROWB + ch * 16, pl);
    }
}

__global__ void __launch_bounds__(256, 1) k_flash()
{
    extern __shared__ char sm[];
    uint32_t sb = smem_to_u32(sm);
    const int tid = threadIdx.x;
    const int lane = tid & 31;
    const int warp = tid >> 5;                 // 8 warps; warp owns q rows warp*16..+15
    const int q0 = blockIdx.x * 128;
    const int bh = blockIdx.y, b = bh >> 4, h = bh & 15;

    // ---- load Q tile (hi/lo) into K buffer, move to register fragments ----
    fa_load_tile(sb + OFF_KH, sb + OFF_KL, g_qh, g_ql,
                 (size_t)(b * NS + q0) * NC + (size_t)h * ND, NC, tid);
    cp_commit();
    cp_wait<0>();
    __syncthreads();

    uint32_t qhf[8][4], qlf[8][4];
    {
        uint32_t rbase = sb + (warp * 16 + (lane & 15)) * FT_ROWB + ((lane >> 4) << 4);
        #pragma unroll
        for (int ks = 0; ks < 8; ks++) {
            ldm_x4(qhf[ks], rbase + OFF_KH + ks * 32);
            ldm_x4(qlf[ks], rbase + OFF_KL + ks * 32);
        }
    }
    __syncthreads();   // done reading Q from Kbuf

    // ---- prime pipeline: K0 then V0 (separate commit groups) ----
    fa_load_tile(sb + OFF_KH, sb + OFF_KL, g_kh, g_kl,
                 (size_t)(b * NS) * NC + (size_t)h * ND, NC, tid);
    cp_commit();
    fa_load_tile(sb + OFF_VH, sb + OFF_VL, g_vth, g_vtl,
                 ((size_t)b * NC + (size_t)h * ND) * NS, NS, tid);
    cp_commit();

    float o[16][4];
    #pragma unroll
    for (int i = 0; i < 16; i++) { o[i][0] = 0.f; o[i][1] = 0.f; o[i][2] = 0.f; o[i][3] = 0.f; }
    float m0 = -1e30f, m1 = -1e30f, l0 = 0.f, l1 = 0.f;

    for (int j = 0; j < 16; j++) {
        // (A) K_j ready (V_j may still be in flight)
        cp_wait<1>();
        __syncthreads();

        // (B) S = Q @ K_j^T  (bf16x3)
        float s[16][4];
        #pragma unroll
        for (int i = 0; i < 16; i++) { s[i][0] = 0.f; s[i][1] = 0.f; s[i][2] = 0.f; s[i][3] = 0.f; }
        #pragma unroll
        for (int ng = 0; ng < 8; ng++) {
            #pragma unroll
            for (int ks = 0; ks < 8; ks++) {
                uint32_t addr = sb + (ng * 16 + (lane & 15)) * FT_ROWB
                              + ((lane >> 4) << 4) + ks * 32;
                uint32_t bh4[4], bl4[4];
                ldm_x4(bh4, addr + OFF_KH);
                ldm_x4(bl4, addr + OFF_KL);
                mma_bf16(s[2 * ng],     qhf[ks], bh4[0], bh4[2]);
                mma_bf16(s[2 * ng],     qhf[ks], bl4[0], bl4[2]);
                mma_bf16(s[2 * ng],     qlf[ks], bh4[0], bh4[2]);
                mma_bf16(s[2 * ng + 1], qhf[ks], bh4[1], bh4[3]);
                mma_bf16(s[2 * ng + 1], qhf[ks], bl4[1], bl4[3]);
                mma_bf16(s[2 * ng + 1], qlf[ks], bh4[1], bh4[3]);
            }
        }
        // (C) Kbuf free -> start K_{j+1}
        __syncthreads();
        if (j + 1 < 16) {
            fa_load_tile(sb + OFF_KH, sb + OFF_KL, g_kh, g_kl,
                         (size_t)(b * NS + (j + 1) * 128) * NC + (size_t)h * ND, NC, tid);
            cp_commit();
        }

        // (D) online softmax (registers only); rows r=lane>>2 (m0/l0), r+8 (m1/l1)
        float mx0 = -1e30f, mx1 = -1e30f;
        #pragma unroll
        for (int i = 0; i < 16; i++) {
            mx0 = fmaxf(mx0, fmaxf(s[i][0], s[i][1]));
            mx1 = fmaxf(mx1, fmaxf(s[i][2], s[i][3]));
        }
        mx0 = fmaxf(mx0, __shfl_xor_sync(0xffffffffu, mx0, 1));
        mx0 = fmaxf(mx0, __shfl_xor_sync(0xffffffffu, mx0, 2));
        mx1 = fmaxf(mx1, __shfl_xor_sync(0xffffffffu, mx1, 1));
        mx1 = fmaxf(mx1, __shfl_xor_sync(0xffffffffu, mx1, 2));
        float nm0 = fmaxf(m0, mx0), nm1 = fmaxf(m1, mx1);
        float a0 = __expf((m0 - nm0) * SM_SCALE);
        float a1 = __expf((m1 - nm1) * SM_SCALE);
        m0 = nm0; m1 = nm1;
        float ps0 = 0.f, ps1 = 0.f;
        #pragma unroll
        for (int i = 0; i < 16; i++) {
            s[i][0] = __expf((s[i][0] - m0) * SM_SCALE);
            s[i][1] = __expf((s[i][1] - m0) * SM_SCALE);
            s[i][2] = __expf((s[i][2] - m1) * SM_SCALE);
            s[i][3] = __expf((s[i][3] - m1) * SM_SCALE);
            ps0 += s[i][0] + s[i][1];
            ps1 += s[i][2] + s[i][3];
        }
        l0 = l0 * a0 + ps0;
        l1 = l1 * a1 + ps1;
        #pragma unroll
        for (int i = 0; i < 16; i++) {
            o[i][0] *= a0; o[i][1] *= a0; o[i][2] *= a1; o[i][3] *= a1;
        }

        // (E) V_j ready
        if (j + 1 < 16) cp_wait<1>(); else cp_wait<0>();
        __syncthreads();

        // (F) ctx += P @ V_j  (P split to bf16 hi/lo in regs, V^T tiles as NT B)
        #pragma unroll
        for (int ks = 0; ks < 8; ks++) {
            uint32_t pah[4], pal[4];
            pack_hl(s[2 * ks][0],     s[2 * ks][1],     pah[0], pal[0]);
            pack_hl(s[2 * ks][2],     s[2 * ks][3],     pah[1], pal[1]);
            pack_hl(s[2 * ks + 1][0], s[2 * ks + 1][1], pah[2], pal[2]);
            pack_hl(s[2 * ks + 1][2], s[2 * ks + 1][3], pah[3], pal[3]);
            #pragma unroll
            for (int ng = 0; ng < 8; ng++) {
                uint32_t addr = sb + OFF_VH + (ng * 16 + (lane & 15)) * FT_ROWB
                              + ((lane >> 4) << 4) + ks * 32;
                uint32_t vh4[4], vl4[4];
                ldm_x4(vh4, addr);
                ldm_x4(vl4, addr + FT_TILE);   // OFF_VL
                mma_bf16(o[2 * ng],     pah, vh4[0], vh4[2]);
                mma_bf16(o[2 * ng],     pah, vl4[0], vl4[2]);
                mma_bf16(o[2 * ng],     pal, vh4[0], vh4[2]);
                mma_bf16(o[2 * ng + 1], pah, vh4[1], vh4[3]);
                mma_bf16(o[2 * ng + 1], pah, vl4[1], vl4[3]);
                mma_bf16(o[2 * ng + 1], pal, vh4[1], vh4[3]);
            }
        }
        // (G) Vbuf free -> start V_{j+1}
        __syncthreads();
        if (j + 1 < 16) {
            fa_load_tile(sb + OFF_VH, sb + OFF_VL, g_vth, g_vtl,
                         ((size_t)b * NC + (size_t)h * ND) * NS + (j + 1) * 128, NS, tid);
            cp_commit();
        }
    }

    // ---- finalize: normalize, split to bf16 hi/lo, write ctx ----
    l0 += __shfl_xor_sync(0xffffffffu, l0, 1);
    l0 += __shfl_xor_sync(0xffffffffu, l0, 2);
    l1 += __shfl_xor_sync(0xffffffffu, l1, 1);
    l1 += __shfl_xor_sync(0xffffffffu, l1, 2);
    float i0 = 1.0f / l0, i1 = 1.0f / l1;

    size_t gr0 = (size_t)(b * NS + q0 + warp * 16 + (lane >> 2));
    #pragma unroll
    for (int nt = 0; nt < 16; nt++) {
        int c = h * ND + nt * 8 + (lane & 3) * 2;
        bf16 h0, h1, lo0, lo1;
        split2(o[nt][0] * i0, h0, lo0);
        split2(o[nt][1] * i0, h1, lo1);
        *(__nv_bfloat162*)(g_ch + gr0 * NC + c) = __nv_bfloat162{h0, h1};
        *(__nv_bfloat162*)(g_cl + gr0 * NC + c) = __nv_bfloat162{lo0, lo1};
        split2(o[nt][2] * i1, h0, lo0);
        split2(o[nt][3] * i1, h1, lo1);
        *(__nv_bfloat162*)(g_ch + (gr0 + 8) * NC + c) = __nv_bfloat162{h0, h1};
        *(__nv_bfloat162*)(g_cl + (gr0 + 8) * NC + c) = __nv_bfloat162{lo0, lo1};
    }
}

// ---------------- elementwise kernels ----------------
__global__ __launch_bounds__(256) void cvt_split(const float* __restrict__ src,
                                                 bf16* __restrict__ hi,
                                                 bf16* __restrict__ lo)
{
    size_t i = (size_t)blockIdx.x * 256 + threadIdx.x;
    float4 v = ((const float4*)src)[i];
    bf16 h0, h1, h2, h3, l0, l1, l2, l3;
    split2(v.x, h0, l0); split2(v.y, h1, l1);
    split2(v.z, h2, l2); split2(v.w, h3, l3);
    __nv_bfloat162* hp = (__nv_bfloat162*)hi;
    __nv_bfloat162* lp = (__nv_bfloat162*)lo;
    hp[2 * i]     = __nv_bfloat162{h0, h1};
    hp[2 * i + 1] = __nv_bfloat162{h2, h3};
    lp[2 * i]     = __nv_bfloat162{l0, l1};
    lp[2 * i + 1] = __nv_bfloat162{l2, l3};
}

// V transpose + split: g_v[(b*S+s), c] -> vT[(b*C+c), s] (hi/lo bf16)
__global__ __launch_bounds__(256) void transpose_split_v()
{
    __shared__ float t[32][33];
    int b = blockIdx.z;
    int s0 = blockIdx.x * 32, c0 = blockIdx.y * 32;
    int tx = threadIdx.x, ty = threadIdx.y;  // 32 x 8
    #pragma unroll
    for (int j = 0; j < 4; j++) {
        int s = s0 + ty + j * 8;
        t[ty + j * 8][tx] = g_v[((size_t)b * NS + s) * NC + c0 + tx];
    }
    __syncthreads();
    #pragma unroll
    for (int j = 0; j < 4; j++) {
        int c = c0 + ty + j * 8;
        float v = t[tx][ty + j * 8];
        bf16 h, l;
        split2(v, h, l);
        size_t o = ((size_t)b * NC + c) * NS + s0 + tx;
        g_vth[o] = h;
        g_vtl[o] = l;
    }
}

// Per-head RMSNorm + RoPE; reads fp32 g_q/g_k, writes split bf16 qh/ql/kh/kl.
__global__ __launch_bounds__(256) void rmsnorm_rope(
    const float* __restrict__ rope,
    const float* __restrict__ gq, const float* __restrict__ gk)
{
    int warp = blockIdx.x * 8 + (threadIdx.x >> 5);
    int lane = threadIdx.x & 31;
    int m = warp >> 4;
    int h = warp & 15;
    int s = m & (NS - 1);

    size_t off = (size_t)m * NC + h * ND;
    const float* qr = g_q + off;
    const float* kr = g_k + off;
    const float* rp = rope + (size_t)s * (ND / 2) * 4;
    int d = lane * 4;

    float4 xq = *(const float4*)(qr + d);
    float4 xk = *(const float4*)(kr + d);
    float ssq = xq.x * xq.x + xq.y * xq.y + xq.z * xq.z + xq.w * xq.w;
    float ssk = xk.x * xk.x + xk.y * xk.y + xk.z * xk.z + xk.w * xk.w;
    #pragma unroll
    for (int o = 16; o; o >>= 1) {
        ssq += __shfl_xor_sync(0xffffffffu, ssq, o);
        ssk += __shfl_xor_sync(0xffffffffu, ssk, o);
    }
    float rq = rsqrtf(ssq * (1.0f / ND) + RMS_EPS);
    float rk = rsqrtf(ssk * (1.0f / ND) + RMS_EPS);

    float4 gqv = *(const float4*)(gq + d);
    float4 gkv = *(const float4*)(gk + d);
    xq.x *= rq * gqv.x; xq.y *= rq * gqv.y; xq.z *= rq * gqv.z; xq.w *= rq * gqv.w;
    xk.x *= rk * gkv.x; xk.y *= rk * gkv.y; xk.z *= rk * gkv.z; xk.w *= rk * gkv.w;

    float4 r0 = *(const float4*)(rp + (size_t)(2 * lane) * 4);
    float4 r1 = *(const float4*)(rp + (size_t)(2 * lane + 1) * 4);
    float4 oq, ok;
    oq.x = r0.x * xq.x + r0.y * xq.y;  oq.y = r0.z * xq.x + r0.w * xq.y;
    oq.z = r1.x * xq.z + r1.y * xq.w;  oq.w = r1.z * xq.z + r1.w * xq.w;
    ok.x = r0.x * xk.x + r0.y * xk.y;  ok.y = r0.z * xk.x + r0.w * xk.y;
    ok.z = r1.x * xk.z + r1.y * xk.w;  ok.w = r1.z * xk.z + r1.w * xk.w;

    bf16 h0, h1, h2, h3, l0, l1, l2, l3;
    split2(oq.x, h0, l0); split2(oq.y, h1, l1);
    split2(oq.z, h2, l2); split2(oq.w, h3, l3);
    *(__nv_bfloat162*)(g_qh + off + d)     = __nv_bfloat162{h0, h1};
    *(__nv_bfloat162*)(g_qh + off + d + 2) = __nv_bfloat162{h2, h3};
    *(__nv_bfloat162*)(g_ql + off + d)     = __nv_bfloat162{l0, l1};
    *(__nv_bfloat162*)(g_ql + off + d + 2) = __nv_bfloat162{l2, l3};

    split2(ok.x, h0, l0); split2(ok.y, h1, l1);
    split2(ok.z, h2, l2); split2(ok.w, h3, l3);
    *(__nv_bfloat162*)(g_kh + off + d)     = __nv_bfloat162{h0, h1};
    *(__nv_bfloat162*)(g_kh + off + d + 2) = __nv_bfloat162{h2, h3};
    *(__nv_bfloat162*)(g_kl + off + d)     = __nv_bfloat162{l0, l1};
    *(__nv_bfloat162*)(g_kl + off + d + 2) = __nv_bfloat162{l2, l3};
}

// ---------------- launch ----------------
extern "C" void kernel_launch(void* const* d_in, const int* in_sizes, int n_in,
                              void* d_out, int out_size)
{
    const float* x    = (const float*)d_in[0];
    const float* rope = (const float*)d_in[1];
    const float* Wq   = (const float*)d_in[2];
    const float* bq   = (const float*)d_in[3];
    const float* Wk   = (const float*)d_in[4];
    const float* bk   = (const float*)d_in[5];
    const float* Wv   = (const float*)d_in[6];
    const float* bv   = (const float*)d_in[7];
    const float* gq   = (const float*)d_in[8];
    const float* gk   = (const float*)d_in[9];
    const float* Wo   = (const float*)d_in[10];
    const float* bo   = (const float*)d_in[11];
    float* out = (float*)d_out;

    cudaFuncSetAttribute(k_gemm_nt, cudaFuncAttributeMaxDynamicSharedMemorySize, GEMM_SMEM);
    cudaFuncSetAttribute(k_flash, cudaFuncAttributeMaxDynamicSharedMemorySize, FLASH_SMEM);

    float *qp, *kp, *vp;
    bf16 *xh, *xl, *wqh, *wql, *wkh, *wkl, *wvh, *wvl, *woh, *wol, *ch, *cl;
    cudaGetSymbolAddress((void**)&qp, g_q);
    cudaGetSymbolAddress((void**)&kp, g_k);
    cudaGetSymbolAddress((void**)&vp, g_v);
    cudaGetSymbolAddress((void**)&xh, g_xh);   cudaGetSymbolAddress((void**)&xl, g_xl);
    cudaGetSymbolAddress((void**)&wqh, g_wqh); cudaGetSymbolAddress((void**)&wql, g_wql);
    cudaGetSymbolAddress((void**)&wkh, g_wkh); cudaGetSymbolAddress((void**)&wkl, g_wkl);
    cudaGetSymbolAddress((void**)&wvh, g_wvh); cudaGetSymbolAddress((void**)&wvl, g_wvl);
    cudaGetSymbolAddress((void**)&woh, g_woh); cudaGetSymbolAddress((void**)&wol, g_wol);
    cudaGetSymbolAddress((void**)&ch, g_ch);   cudaGetSymbolAddress((void**)&cl, g_cl);

    const size_t nX = (size_t)NM * NC;       // 8M elems
    const size_t nW = (size_t)NC * NC;       // 4M elems

    cvt_split<<<(unsigned)(nX / 1024), 256>>>(x, xh, xl);
    cvt_split<<<(unsigned)(nW / 1024), 256>>>(Wq, wqh, wql);
    cvt_split<<<(unsigned)(nW / 1024), 256>>>(Wk, wkh, wkl);
    cvt_split<<<(unsigned)(nW / 1024), 256>>>(Wv, wvh, wvl);
    cvt_split<<<(unsigned)(nW / 1024), 256>>>(Wo, woh, wol);

    dim3 gProj(NC / 128, NM / 128);          // (16, 32)
    k_gemm_nt<<<gProj, 256, GEMM_SMEM>>>(xh, xl, wqh, wql, bq, qp);
    k_gemm_nt<<<gProj, 256, GEMM_SMEM>>>(xh, xl, wkh, wkl, bk, kp);
    k_gemm_nt<<<gProj, 256, GEMM_SMEM>>>(xh, xl, wvh, wvl, bv, vp);

    rmsnorm_rope<<<(NM * NH) / 8, 256>>>(rope, gq, gk);
    transpose_split_v<<<dim3(NS / 32, NC / 32, NB), dim3(32, 8)>>>();

    k_flash<<<dim3(NS / 128, NBH), 256, FLASH_SMEM>>>();

    k_gemm_nt<<<gProj, 256, GEMM_SMEM>>>(ch, cl, woh, wol, bo, out);
}

// round 7
// speedup vs baseline: 2.7565x; 1.2325x over previous
#include <cuda_runtime.h>
#include <cuda_bf16.h>
#include <cuda_fp16.h>
#include <math.h>
#include <stdint.h>
#include <stddef.h>

#define NB 2
#define NS 2048
#define NC 2048
#define ND 128
#define NH 16
#define NM (NB * NS)       // 4096
#define NBH (NB * NH)      // 32
#define RMS_EPS 1.1920928955078125e-07f
#define SM_SCALE 0.08838834764831844f

typedef __nv_bfloat16 bf16;
typedef __half f16;

// ---------------- scratch (device globals; no allocation) ----------------
__device__ float g_q[(size_t)NM * NC];
__device__ float g_k[(size_t)NM * NC];
__device__ float g_v[(size_t)NM * NC];

// f16 operands (QKV projections, PV value tile)
__device__ f16 g_xhf[(size_t)NM * NC], g_xlf[(size_t)NM * NC];
__device__ f16 g_wqf[(size_t)NC * NC], g_wkf[(size_t)NC * NC], g_wvf[(size_t)NC * NC];
__device__ f16 g_vtf[(size_t)NB * NC * NS];

// bf16 split operands (scores q/k, ctx, Wo)
__device__ bf16 g_woh[(size_t)NC * NC], g_wol[(size_t)NC * NC];
__device__ bf16 g_qh[(size_t)NM * NC],  g_ql[(size_t)NM * NC];
__device__ bf16 g_kh[(size_t)NM * NC],  g_kl[(size_t)NM * NC];
__device__ bf16 g_ch[(size_t)NM * NC],  g_cl[(size_t)NM * NC];

// ---------------- PTX helpers (sm_80-era, family-target safe) -------------
__device__ __forceinline__ uint32_t smem_to_u32(const void* p) {
    uint32_t a;
    asm("{ .reg .u64 t; cvta.to.shared.u64 t, %1; cvt.u32.u64 %0, t; }"
        : "=r"(a) : "l"(p));
    return a;
}
__device__ __forceinline__ void cp_async16(uint32_t dst, const void* src) {
    asm volatile("cp.async.cg.shared.global [%0], [%1], 16;"
                 :: "r"(dst), "l"(src) : "memory");
}
__device__ __forceinline__ void cp_commit() {
    asm volatile("cp.async.commit_group;" ::: "memory");
}
template <int N>
__device__ __forceinline__ void cp_wait() {
    asm volatile("cp.async.wait_group %0;" :: "n"(N) : "memory");
}
__device__ __forceinline__ void ldm_x4(uint32_t (&r)[4], uint32_t addr) {
    asm volatile("ldmatrix.sync.aligned.m8n8.x4.shared.b16 {%0,%1,%2,%3}, [%4];"
                 : "=r"(r[0]), "=r"(r[1]), "=r"(r[2]), "=r"(r[3]) : "r"(addr));
}
__device__ __forceinline__ void mma_bf16(float (&d)[4], const uint32_t (&a)[4],
                                         uint32_t b0, uint32_t b1) {
    asm volatile("mma.sync.aligned.m16n8k16.row.col.f32.bf16.bf16.f32 "
                 "{%0,%1,%2,%3}, {%4,%5,%6,%7}, {%8,%9}, {%0,%1,%2,%3};"
                 : "+f"(d[0]), "+f"(d[1]), "+f"(d[2]), "+f"(d[3])
                 : "r"(a[0]), "r"(a[1]), "r"(a[2]), "r"(a[3]), "r"(b0), "r"(b1));
}
__device__ __forceinline__ void mma_f16(float (&d)[4], const uint32_t (&a)[4],
                                        uint32_t b0, uint32_t b1) {
    asm volatile("mma.sync.aligned.m16n8k16.row.col.f32.f16.f16.f32 "
                 "{%0,%1,%2,%3}, {%4,%5,%6,%7}, {%8,%9}, {%0,%1,%2,%3};"
                 : "+f"(d[0]), "+f"(d[1]), "+f"(d[2]), "+f"(d[3])
                 : "r"(a[0]), "r"(a[1]), "r"(a[2]), "r"(a[3]), "r"(b0), "r"(b1));
}

__device__ __forceinline__ void split2(float x, bf16& h, bf16& l) {
    h = __float2bfloat16_rn(x);
    l = __float2bfloat16_rn(x - __bfloat162float(h));
}
__device__ __forceinline__ void split2f(float x, f16& h, f16& l) {
    h = __float2half_rn(x);
    l = __float2half_rn(x - __half2float(h));
}
// pack two floats into f16x2 hi-part and residual-part registers
__device__ __forceinline__ void pack_hl_f16(float x, float y, uint32_t& hi, uint32_t& lo) {
    f16 hx, lx, hy, ly;
    split2f(x, hx, lx);
    split2f(y, hy, ly);
    __half2 H{hx, hy}, L{lx, ly};
    hi = *reinterpret_cast<uint32_t*>(&H);
    lo = *reinterpret_cast<uint32_t*>(&L);
}

// ---------------- common tiling constants ----------------
#define KCH 32
#define ROW_BYTES 80
#define TILE_BYTES (128 * ROW_BYTES)        // 10240

__device__ __forceinline__ void load_tile_async(uint32_t smbase, const void* g,
                                                int ld, int k0, int tid) {
    const char* gp = (const char*)g + (size_t)k0 * 2;
    #pragma unroll
    for (int j = 0; j < 2; j++) {
        int i = tid + j * 256;
        int row = i >> 2;
        int c = i & 3;
        cp_async16(smbase + row * ROW_BYTES + c * 16,
                   gp + (size_t)row * ld * 2 + c * 16);
    }
}

// =========================================================================
// bf16x3 HMMA GEMM (out-proj): 128x128 tile, 256 thr, K-chunk 32
// =========================================================================
#define STAGE_BYTES (4 * TILE_BYTES)        // 40960
#define GEMM_SMEM (2 * STAGE_BYTES)         // 81920

__global__ __launch_bounds__(256)
void k_gemm_nt(const bf16* __restrict__ AhG, const bf16* __restrict__ AlG,
               const bf16* __restrict__ BhG, const bf16* __restrict__ BlG,
               const float* __restrict__ biasG, float* __restrict__ OutG)
{
    size_t bm = (size_t)blockIdx.y * 128;
    size_t bn = (size_t)blockIdx.x * 128;
    const bf16* Ah = AhG + bm * NC;
    const bf16* Al = AlG + bm * NC;
    const bf16* Bh = BhG + bn * NC;
    const bf16* Bl = BlG + bn * NC;
    const float* bias = biasG + bn;
    float* Out = OutG + bm * NC + bn;

    extern __shared__ char sm[];
    uint32_t sb = smem_to_u32(sm);
    const int tid = threadIdx.x;
    const int lane = tid & 31;
    const int warp = tid >> 5;
    const int wm = warp >> 1;
    const int wn = warp & 1;

    float acc[2][8][4];
    #pragma unroll
    for (int mt = 0; mt < 2; mt++)
        #pragma unroll
        for (int nt = 0; nt < 8; nt++)
            #pragma unroll
            for (int j = 0; j < 4; j++) acc[mt][nt][j] = 0.0f;

    const int nch = NC / KCH;

    auto load_chunk = [&](int ch, int s) {
        uint32_t base = sb + s * STAGE_BYTES;
        int k0 = ch * KCH;
        load_tile_async(base,                  Ah, NC, k0, tid);
        load_tile_async(base + TILE_BYTES,     Al, NC, k0, tid);
        load_tile_async(base + 2 * TILE_BYTES, Bh, NC, k0, tid);
        load_tile_async(base + 3 * TILE_BYTES, Bl, NC, k0, tid);
    };

    load_chunk(0, 0);
    cp_commit();

    for (int ch = 0; ch < nch; ch++) {
        int cur = ch & 1;
        if (ch + 1 < nch) {
            load_chunk(ch + 1, cur ^ 1);
            cp_commit();
            cp_wait<1>();
        } else {
            cp_wait<0>();
        }
        __syncthreads();

        uint32_t base = sb + cur * STAGE_BYTES;
        #pragma unroll
        for (int ks = 0; ks < 2; ks++) {
            uint32_t koff = (uint32_t)(ks * 32 + (lane >> 4) * 16);
            uint32_t ah[2][4], al[2][4];
            #pragma unroll
            for (int mt = 0; mt < 2; mt++) {
                uint32_t r = wm * 32 + mt * 16 + (lane & 15);
                uint32_t addr = base + r * ROW_BYTES + koff;
                ldm_x4(ah[mt], addr);
                ldm_x4(al[mt], addr + TILE_BYTES);
            }
            uint32_t bh[4][4], bl[4][4];
            #pragma unroll
            for (int ng = 0; ng < 4; ng++) {
                uint32_t r = wn * 64 + ng * 16 + (lane & 15);
                uint32_t addr = base + 2 * TILE_BYTES + r * ROW_BYTES + koff;
                ldm_x4(bh[ng], addr);
                ldm_x4(bl[ng], addr + TILE_BYTES);
            }
            #pragma unroll
            for (int mt = 0; mt < 2; mt++)
                #pragma unroll
                for (int ng = 0; ng < 4; ng++) {
                    mma_bf16(acc[mt][2 * ng],     ah[mt], bh[ng][0], bh[ng][2]);
                    mma_bf16(acc[mt][2 * ng],     ah[mt], bl[ng][0], bl[ng][2]);
                    mma_bf16(acc[mt][2 * ng],     al[mt], bh[ng][0], bh[ng][2]);
                    mma_bf16(acc[mt][2 * ng + 1], ah[mt], bh[ng][1], bh[ng][3]);
                    mma_bf16(acc[mt][2 * ng + 1], ah[mt], bl[ng][1], bl[ng][3]);
                    mma_bf16(acc[mt][2 * ng + 1], al[mt], bh[ng][1], bh[ng][3]);
                }
        }
        __syncthreads();
    }

    #pragma unroll
    for (int mt = 0; mt < 2; mt++) {
        int r0 = wm * 32 + mt * 16 + (lane >> 2);
        #pragma unroll
        for (int nt = 0; nt < 8; nt++) {
            int c = wn * 64 + nt * 8 + (lane & 3) * 2;
            float bx = bias[c], by = bias[c + 1];
            float2 v0 = { acc[mt][nt][0] + bx, acc[mt][nt][1] + by };
            float2 v1 = { acc[mt][nt][2] + bx, acc[mt][nt][3] + by };
            *(float2*)(Out + (size_t)r0 * NC + c) = v0;
            *(float2*)(Out + (size_t)(r0 + 8) * NC + c) = v1;
        }
    }
}

// =========================================================================
// f16 2-term GEMM (QKV projections): A split 2xf16, B single f16
// =========================================================================
#define F16_STAGE (3 * TILE_BYTES)          // 30720
#define F16_SMEM (2 * F16_STAGE)            // 61440

__global__ __launch_bounds__(256)
void k_gemm_nt_f16(const f16* __restrict__ AhG, const f16* __restrict__ AlG,
                   const f16* __restrict__ BfG, const float* __restrict__ biasG,
                   float* __restrict__ OutG)
{
    size_t bm = (size_t)blockIdx.y * 128;
    size_t bn = (size_t)blockIdx.x * 128;
    const f16* Ah = AhG + bm * NC;
    const f16* Al = AlG + bm * NC;
    const f16* Bf = BfG + bn * NC;
    const float* bias = biasG + bn;
    float* Out = OutG + bm * NC + bn;

    extern __shared__ char sm[];
    uint32_t sb = smem_to_u32(sm);
    const int tid = threadIdx.x;
    const int lane = tid & 31;
    const int warp = tid >> 5;
    const int wm = warp >> 1;
    const int wn = warp & 1;

    float acc[2][8][4];
    #pragma unroll
    for (int mt = 0; mt < 2; mt++)
        #pragma unroll
        for (int nt = 0; nt < 8; nt++)
            #pragma unroll
            for (int j = 0; j < 4; j++) acc[mt][nt][j] = 0.0f;

    const int nch = NC / KCH;

    auto load_chunk = [&](int ch, int s) {
        uint32_t base = sb + s * F16_STAGE;
        int k0 = ch * KCH;
        load_tile_async(base,                  Ah, NC, k0, tid);
        load_tile_async(base + TILE_BYTES,     Al, NC, k0, tid);
        load_tile_async(base + 2 * TILE_BYTES, Bf, NC, k0, tid);
    };

    load_chunk(0, 0);
    cp_commit();

    for (int ch = 0; ch < nch; ch++) {
        int cur = ch & 1;
        if (ch + 1 < nch) {
            load_chunk(ch + 1, cur ^ 1);
            cp_commit();
            cp_wait<1>();
        } else {
            cp_wait<0>();
        }
        __syncthreads();

        uint32_t base = sb + cur * F16_STAGE;
        #pragma unroll
        for (int ks = 0; ks < 2; ks++) {
            uint32_t koff = (uint32_t)(ks * 32 + (lane >> 4) * 16);
            uint32_t ah[2][4], al[2][4];
            #pragma unroll
            for (int mt = 0; mt < 2; mt++) {
                uint32_t r = wm * 32 + mt * 16 + (lane & 15);
                uint32_t addr = base + r * ROW_BYTES + koff;
                ldm_x4(ah[mt], addr);
                ldm_x4(al[mt], addr + TILE_BYTES);
            }
            uint32_t bfr[4][4];
            #pragma unroll
            for (int ng = 0; ng < 4; ng++) {
                uint32_t r = wn * 64 + ng * 16 + (lane & 15);
                ldm_x4(bfr[ng], base + 2 * TILE_BYTES + r * ROW_BYTES + koff);
            }
            #pragma unroll
            for (int mt = 0; mt < 2; mt++)
                #pragma unroll
                for (int ng = 0; ng < 4; ng++) {
                    mma_f16(acc[mt][2 * ng],     ah[mt], bfr[ng][0], bfr[ng][2]);
                    mma_f16(acc[mt][2 * ng],     al[mt], bfr[ng][0], bfr[ng][2]);
                    mma_f16(acc[mt][2 * ng + 1], ah[mt], bfr[ng][1], bfr[ng][3]);
                    mma_f16(acc[mt][2 * ng + 1], al[mt], bfr[ng][1], bfr[ng][3]);
                }
        }
        __syncthreads();
    }

    #pragma unroll
    for (int mt = 0; mt < 2; mt++) {
        int r0 = wm * 32 + mt * 16 + (lane >> 2);
        #pragma unroll
        for (int nt = 0; nt < 8; nt++) {
            int c = wn * 64 + nt * 8 + (lane & 3) * 2;
            float bx = bias[c], by = bias[c + 1];
            float2 v0 = { acc[mt][nt][0] + bx, acc[mt][nt][1] + by };
            float2 v1 = { acc[mt][nt][2] + bx, acc[mt][nt][3] + by };
            *(float2*)(Out + (size_t)r0 * NC + c) = v0;
            *(float2*)(Out + (size_t)(r0 + 8) * NC + c) = v1;
        }
    }
}

// =========================================================================
// Flash attention: scores (bf16x3) + online softmax + PV (f16 2-term)
// =========================================================================
#define FT_ROWB 272                          // 256B row + 16B pad
#define FT_TILE (128 * FT_ROWB)              // 34816
#define OFF_KH 0
#define OFF_KL FT_TILE
#define OFF_VF (2 * FT_TILE)
#define FLASH_SMEM (3 * FT_TILE)             // 104448

__device__ __forceinline__ void fa_load_pair(uint32_t dsthi, uint32_t dstlo,
                                             const bf16* gh, const bf16* gl,
                                             size_t rowbase, size_t ldrow, int tid)
{
    #pragma unroll
    for (int i = 0; i < 8; i++) {
        int idx = tid + i * 256;
        int row = idx >> 4;
        int ch = idx & 15;
        const char* ph = (const char*)(gh + rowbase + (size_t)row * ldrow) + ch * 16;
        const char* pl = (const char*)(gl + rowbase + (size_t)row * ldrow) + ch * 16;
        cp_async16(dsthi + row * FT_ROWB + ch * 16, ph);
        cp_async16(dstlo + row * FT_ROWB + ch * 16, pl);
    }
}
__device__ __forceinline__ void fa_load_one(uint32_t dst, const f16* g,
                                            size_t rowbase, size_t ldrow, int tid)
{
    #pragma unroll
    for (int i = 0; i < 8; i++) {
        int idx = tid + i * 256;
        int row = idx >> 4;
        int ch = idx & 15;
        cp_async16(dst + row * FT_ROWB + ch * 16,
                   (const char*)(g + rowbase + (size_t)row * ldrow) + ch * 16);
    }
}

__global__ void __launch_bounds__(256, 1) k_flash()
{
    extern __shared__ char sm[];
    uint32_t sb = smem_to_u32(sm);
    const int tid = threadIdx.x;
    const int lane = tid & 31;
    const int warp = tid >> 5;
    const int q0 = blockIdx.x * 128;
    const int bh = blockIdx.y, b = bh >> 4, h = bh & 15;

    // ---- load Q tile (hi/lo) into K buffer, move to register fragments ----
    fa_load_pair(sb + OFF_KH, sb + OFF_KL, g_qh, g_ql,
                 (size_t)(b * NS + q0) * NC + (size_t)h * ND, NC, tid);
    cp_commit();
    cp_wait<0>();
    __syncthreads();

    uint32_t qhf[8][4], qlf[8][4];
    {
        uint32_t rbase = sb + (warp * 16 + (lane & 15)) * FT_ROWB + ((lane >> 4) << 4);
        #pragma unroll
        for (int ks = 0; ks < 8; ks++) {
            ldm_x4(qhf[ks], rbase + OFF_KH + ks * 32);
            ldm_x4(qlf[ks], rbase + OFF_KL + ks * 32);
        }
    }
    __syncthreads();

    // ---- prime pipeline: K0 then V0 (separate commit groups) ----
    fa_load_pair(sb + OFF_KH, sb + OFF_KL, g_kh, g_kl,
                 (size_t)(b * NS) * NC + (size_t)h * ND, NC, tid);
    cp_commit();
    fa_load_one(sb + OFF_VF, g_vtf,
                ((size_t)b * NC + (size_t)h * ND) * NS, NS, tid);
    cp_commit();

    float o[16][4];
    #pragma unroll
    for (int i = 0; i < 16; i++) { o[i][0] = 0.f; o[i][1] = 0.f; o[i][2] = 0.f; o[i][3] = 0.f; }
    float m0 = -1e30f, m1 = -1e30f, l0 = 0.f, l1 = 0.f;

    for (int j = 0; j < 16; j++) {
        // (A) K_j ready
        cp_wait<1>();
        __syncthreads();

        // (B) S = Q @ K_j^T  (bf16x3)
        float s[16][4];
        #pragma unroll
        for (int i = 0; i < 16; i++) { s[i][0] = 0.f; s[i][1] = 0.f; s[i][2] = 0.f; s[i][3] = 0.f; }
        #pragma unroll
        for (int ng = 0; ng < 8; ng++) {
            #pragma unroll
            for (int ks = 0; ks < 8; ks++) {
                uint32_t addr = sb + (ng * 16 + (lane & 15)) * FT_ROWB
                              + ((lane >> 4) << 4) + ks * 32;
                uint32_t bh4[4], bl4[4];
                ldm_x4(bh4, addr + OFF_KH);
                ldm_x4(bl4, addr + OFF_KL);
                mma_bf16(s[2 * ng],     qhf[ks], bh4[0], bh4[2]);
                mma_bf16(s[2 * ng],     qhf[ks], bl4[0], bl4[2]);
                mma_bf16(s[2 * ng],     qlf[ks], bh4[0], bh4[2]);
                mma_bf16(s[2 * ng + 1], qhf[ks], bh4[1], bh4[3]);
                mma_bf16(s[2 * ng + 1], qhf[ks], bl4[1], bl4[3]);
                mma_bf16(s[2 * ng + 1], qlf[ks], bh4[1], bh4[3]);
            }
        }
        // (C) Kbuf free -> start K_{j+1}
        __syncthreads();
        if (j + 1 < 16) {
            fa_load_pair(sb + OFF_KH, sb + OFF_KL, g_kh, g_kl,
                         (size_t)(b * NS + (j + 1) * 128) * NC + (size_t)h * ND, NC, tid);
            cp_commit();
        }

        // (D) online softmax
        float mx0 = -1e30f, mx1 = -1e30f;
        #pragma unroll
        for (int i = 0; i < 16; i++) {
            mx0 = fmaxf(mx0, fmaxf(s[i][0], s[i][1]));
            mx1 = fmaxf(mx1, fmaxf(s[i][2], s[i][3]));
        }
        mx0 = fmaxf(mx0, __shfl_xor_sync(0xffffffffu, mx0, 1));
        mx0 = fmaxf(mx0, __shfl_xor_sync(0xffffffffu, mx0, 2));
        mx1 = fmaxf(mx1, __shfl_xor_sync(0xffffffffu, mx1, 1));
        mx1 = fmaxf(mx1, __shfl_xor_sync(0xffffffffu, mx1, 2));
        float nm0 = fmaxf(m0, mx0), nm1 = fmaxf(m1, mx1);
        float a0 = __expf((m0 - nm0) * SM_SCALE);
        float a1 = __expf((m1 - nm1) * SM_SCALE);
        m0 = nm0; m1 = nm1;
        float ps0 = 0.f, ps1 = 0.f;
        #pragma unroll
        for (int i = 0; i < 16; i++) {
            s[i][0] = __expf((s[i][0] - m0) * SM_SCALE);
            s[i][1] = __expf((s[i][1] - m0) * SM_SCALE);
            s[i][2] = __expf((s[i][2] - m1) * SM_SCALE);
            s[i][3] = __expf((s[i][3] - m1) * SM_SCALE);
            ps0 += s[i][0] + s[i][1];
            ps1 += s[i][2] + s[i][3];
        }
        l0 = l0 * a0 + ps0;
        l1 = l1 * a1 + ps1;
        #pragma unroll
        for (int i = 0; i < 16; i++) {
            o[i][0] *= a0; o[i][1] *= a0; o[i][2] *= a1; o[i][3] *= a1;
        }

        // (E) V_j ready
        if (j + 1 < 16) cp_wait<1>(); else cp_wait<0>();
        __syncthreads();

        // (F) ctx += P @ V_j  (P split f16 hi/lo in regs, V single f16)
        #pragma unroll
        for (int ks = 0; ks < 8; ks++) {
            uint32_t pah[4], pal[4];
            pack_hl_f16(s[2 * ks][0],     s[2 * ks][1],     pah[0], pal[0]);
            pack_hl_f16(s[2 * ks][2],     s[2 * ks][3],     pah[1], pal[1]);
            pack_hl_f16(s[2 * ks + 1][0], s[2 * ks + 1][1], pah[2], pal[2]);
            pack_hl_f16(s[2 * ks + 1][2], s[2 * ks + 1][3], pah[3], pal[3]);
            #pragma unroll
            for (int ng = 0; ng < 8; ng++) {
                uint32_t addr = sb + OFF_VF + (ng * 16 + (lane & 15)) * FT_ROWB
                              + ((lane >> 4) << 4) + ks * 32;
                uint32_t vf4[4];
                ldm_x4(vf4, addr);
                mma_f16(o[2 * ng],     pah, vf4[0], vf4[2]);
                mma_f16(o[2 * ng],     pal, vf4[0], vf4[2]);
                mma_f16(o[2 * ng + 1], pah, vf4[1], vf4[3]);
                mma_f16(o[2 * ng + 1], pal, vf4[1], vf4[3]);
            }
        }
        // (G) Vbuf free -> start V_{j+1}
        __syncthreads();
        if (j + 1 < 16) {
            fa_load_one(sb + OFF_VF, g_vtf,
                        ((size_t)b * NC + (size_t)h * ND) * NS + (j + 1) * 128, NS, tid);
            cp_commit();
        }
    }

    // ---- finalize: normalize, split to bf16 hi/lo, write ctx ----
    l0 += __shfl_xor_sync(0xffffffffu, l0, 1);
    l0 += __shfl_xor_sync(0xffffffffu, l0, 2);
    l1 += __shfl_xor_sync(0xffffffffu, l1, 1);
    l1 += __shfl_xor_sync(0xffffffffu, l1, 2);
    float i0 = 1.0f / l0, i1 = 1.0f / l1;

    size_t gr0 = (size_t)(b * NS + q0 + warp * 16 + (lane >> 2));
    #pragma unroll
    for (int nt = 0; nt < 16; nt++) {
        int c = h * ND + nt * 8 + (lane & 3) * 2;
        bf16 h0, h1, lo0, lo1;
        split2(o[nt][0] * i0, h0, lo0);
        split2(o[nt][1] * i0, h1, lo1);
        *(__nv_bfloat162*)(g_ch + gr0 * NC + c) = __nv_bfloat162{h0, h1};
        *(__nv_bfloat162*)(g_cl + gr0 * NC + c) = __nv_bfloat162{lo0, lo1};
        split2(o[nt][2] * i1, h0, lo0);
        split2(o[nt][3] * i1, h1, lo1);
        *(__nv_bfloat162*)(g_ch + (gr0 + 8) * NC + c) = __nv_bfloat162{h0, h1};
        *(__nv_bfloat162*)(g_cl + (gr0 + 8) * NC + c) = __nv_bfloat162{lo0, lo1};
    }
}

// ---------------- elementwise kernels ----------------
__global__ __launch_bounds__(256) void cvt_split(const float* __restrict__ src,
                                                 bf16* __restrict__ hi,
                                                 bf16* __restrict__ lo)
{
    size_t i = (size_t)blockIdx.x * 256 + threadIdx.x;
    float4 v = ((const float4*)src)[i];
    bf16 h0, h1, h2, h3, l0, l1, l2, l3;
    split2(v.x, h0, l0); split2(v.y, h1, l1);
    split2(v.z, h2, l2); split2(v.w, h3, l3);
    __nv_bfloat162* hp = (__nv_bfloat162*)hi;
    __nv_bfloat162* lp = (__nv_bfloat162*)lo;
    hp[2 * i]     = __nv_bfloat162{h0, h1};
    hp[2 * i + 1] = __nv_bfloat162{h2, h3};
    lp[2 * i]     = __nv_bfloat162{l0, l1};
    lp[2 * i + 1] = __nv_bfloat162{l2, l3};
}

__global__ __launch_bounds__(256) void cvt_split_f16(const float* __restrict__ src,
                                                     f16* __restrict__ hi,
                                                     f16* __restrict__ lo)
{
    size_t i = (size_t)blockIdx.x * 256 + threadIdx.x;
    float4 v = ((const float4*)src)[i];
    f16 h0, h1, h2, h3, l0, l1, l2, l3;
    split2f(v.x, h0, l0); split2f(v.y, h1, l1);
    split2f(v.z, h2, l2); split2f(v.w, h3, l3);
    __half2* hp = (__half2*)hi;
    __half2* lp = (__half2*)lo;
    hp[2 * i]     = __half2{h0, h1};
    hp[2 * i + 1] = __half2{h2, h3};
    lp[2 * i]     = __half2{l0, l1};
    lp[2 * i + 1] = __half2{l2, l3};
}

__global__ __launch_bounds__(256) void cvt_f16(const float* __restrict__ src,
                                               f16* __restrict__ dst)
{
    size_t i = (size_t)blockIdx.x * 256 + threadIdx.x;
    float4 v = ((const float4*)src)[i];
    __half2* dp = (__half2*)dst;
    dp[2 * i]     = __half2{__float2half_rn(v.x), __float2half_rn(v.y)};
    dp[2 * i + 1] = __half2{__float2half_rn(v.z), __float2half_rn(v.w)};
}

// V transpose to single f16: g_v[(b*S+s), c] -> vT[(b*C+c), s]
__global__ __launch_bounds__(256) void transpose_v_f16()
{
    __shared__ float t[32][33];
    int b = blockIdx.z;
    int s0 = blockIdx.x * 32, c0 = blockIdx.y * 32;
    int tx = threadIdx.x, ty = threadIdx.y;  // 32 x 8
    #pragma unroll
    for (int j = 0; j < 4; j++) {
        int s = s0 + ty + j * 8;
        t[ty + j * 8][tx] = g_v[((size_t)b * NS + s) * NC + c0 + tx];
    }
    __syncthreads();
    #pragma unroll
    for (int j = 0; j < 4; j++) {
        int c = c0 + ty + j * 8;
        g_vtf[((size_t)b * NC + c) * NS + s0 + tx] = __float2half_rn(t[tx][ty + j * 8]);
    }
}

// Per-head RMSNorm + RoPE; reads fp32 g_q/g_k, writes split bf16 qh/ql/kh/kl.
__global__ __launch_bounds__(256) void rmsnorm_rope(
    const float* __restrict__ rope,
    const float* __restrict__ gq, const float* __restrict__ gk)
{
    int warp = blockIdx.x * 8 + (threadIdx.x >> 5);
    int lane = threadIdx.x & 31;
    int m = warp >> 4;
    int h = warp & 15;
    int s = m & (NS - 1);

    size_t off = (size_t)m * NC + h * ND;
    const float* qr = g_q + off;
    const float* kr = g_k + off;
    const float* rp = rope + (size_t)s * (ND / 2) * 4;
    int d = lane * 4;

    float4 xq = *(const float4*)(qr + d);
    float4 xk = *(const float4*)(kr + d);
    float ssq = xq.x * xq.x + xq.y * xq.y + xq.z * xq.z + xq.w * xq.w;
    float ssk = xk.x * xk.x + xk.y * xk.y + xk.z * xk.z + xk.w * xk.w;
    #pragma unroll
    for (int o = 16; o; o >>= 1) {
        ssq += __shfl_xor_sync(0xffffffffu, ssq, o);
        ssk += __shfl_xor_sync(0xffffffffu, ssk, o);
    }
    float rq = rsqrtf(ssq * (1.0f / ND) + RMS_EPS);
    float rk = rsqrtf(ssk * (1.0f / ND) + RMS_EPS);

    float4 gqv = *(const float4*)(gq + d);
    float4 gkv = *(const float4*)(gk + d);
    xq.x *= rq * gqv.x; xq.y *= rq * gqv.y; xq.z *= rq * gqv.z; xq.w *= rq * gqv.w;
    xk.x *= rk * gkv.x; xk.y *= rk * gkv.y; xk.z *= rk * gkv.z; xk.w *= rk * gkv.w;

    float4 r0 = *(const float4*)(rp + (size_t)(2 * lane) * 4);
    float4 r1 = *(const float4*)(rp + (size_t)(2 * lane + 1) * 4);
    float4 oq, ok;
    oq.x = r0.x * xq.x + r0.y * xq.y;  oq.y = r0.z * xq.x + r0.w * xq.y;
    oq.z = r1.x * xq.z + r1.y * xq.w;  oq.w = r1.z * xq.z + r1.w * xq.w;
    ok.x = r0.x * xk.x + r0.y * xk.y;  ok.y = r0.z * xk.x + r0.w * xk.y;
    ok.z = r1.x * xk.z + r1.y * xk.w;  ok.w = r1.z * xk.z + r1.w * xk.w;

    bf16 h0, h1, h2, h3, l0, l1, l2, l3;
    split2(oq.x, h0, l0); split2(oq.y, h1, l1);
    split2(oq.z, h2, l2); split2(oq.w, h3, l3);
    *(__nv_bfloat162*)(g_qh + off + d)     = __nv_bfloat162{h0, h1};
    *(__nv_bfloat162*)(g_qh + off + d + 2) = __nv_bfloat162{h2, h3};
    *(__nv_bfloat162*)(g_ql + off + d)     = __nv_bfloat162{l0, l1};
    *(__nv_bfloat162*)(g_ql + off + d + 2) = __nv_bfloat162{l2, l3};

    split2(ok.x, h0, l0); split2(ok.y, h1, l1);
    split2(ok.z, h2, l2); split2(ok.w, h3, l3);
    *(__nv_bfloat162*)(g_kh + off + d)     = __nv_bfloat162{h0, h1};
    *(__nv_bfloat162*)(g_kh + off + d + 2) = __nv_bfloat162{h2, h3};
    *(__nv_bfloat162*)(g_kl + off + d)     = __nv_bfloat162{l0, l1};
    *(__nv_bfloat162*)(g_kl + off + d + 2) = __nv_bfloat162{l2, l3};
}

// ---------------- launch ----------------
extern "C" void kernel_launch(void* const* d_in, const int* in_sizes, int n_in,
                              void* d_out, int out_size)
{
    const float* x    = (const float*)d_in[0];
    const float* rope = (const float*)d_in[1];
    const float* Wq   = (const float*)d_in[2];
    const float* bq   = (const float*)d_in[3];
    const float* Wk   = (const float*)d_in[4];
    const float* bk   = (const float*)d_in[5];
    const float* Wv   = (const float*)d_in[6];
    const float* bv   = (const float*)d_in[7];
    const float* gq   = (const float*)d_in[8];
    const float* gk   = (const float*)d_in[9];
    const float* Wo   = (const float*)d_in[10];
    const float* bo   = (const float*)d_in[11];
    float* out = (float*)d_out;

    cudaFuncSetAttribute(k_gemm_nt, cudaFuncAttributeMaxDynamicSharedMemorySize, GEMM_SMEM);
    cudaFuncSetAttribute(k_gemm_nt_f16, cudaFuncAttributeMaxDynamicSharedMemorySize, F16_SMEM);
    cudaFuncSetAttribute(k_flash, cudaFuncAttributeMaxDynamicSharedMemorySize, FLASH_SMEM);

    float *qp, *kp, *vp;
    f16 *xhf, *xlf, *wqf, *wkf, *wvf;
    bf16 *woh, *wol, *ch, *cl;
    cudaGetSymbolAddress((void**)&qp, g_q);
    cudaGetSymbolAddress((void**)&kp, g_k);
    cudaGetSymbolAddress((void**)&vp, g_v);
    cudaGetSymbolAddress((void**)&xhf, g_xhf); cudaGetSymbolAddress((void**)&xlf, g_xlf);
    cudaGetSymbolAddress((void**)&wqf, g_wqf); cudaGetSymbolAddress((void**)&wkf, g_wkf);
    cudaGetSymbolAddress((void**)&wvf, g_wvf);
    cudaGetSymbolAddress((void**)&woh, g_woh); cudaGetSymbolAddress((void**)&wol, g_wol);
    cudaGetSymbolAddress((void**)&ch, g_ch);   cudaGetSymbolAddress((void**)&cl, g_cl);

    const size_t nX = (size_t)NM * NC;       // 8M elems
    const size_t nW = (size_t)NC * NC;       // 4M elems

    cvt_split_f16<<<(unsigned)(nX / 1024), 256>>>(x, xhf, xlf);
    cvt_f16<<<(unsigned)(nW / 1024), 256>>>(Wq, wqf);
    cvt_f16<<<(unsigned)(nW / 1024), 256>>>(Wk, wkf);
    cvt_f16<<<(unsigned)(nW / 1024), 256>>>(Wv, wvf);
    cvt_split<<<(unsigned)(nW / 1024), 256>>>(Wo, woh, wol);

    dim3 gProj(NC / 128, NM / 128);          // (16, 32)
    k_gemm_nt_f16<<<gProj, 256, F16_SMEM>>>(xhf, xlf, wqf, bq, qp);
    k_gemm_nt_f16<<<gProj, 256, F16_SMEM>>>(xhf, xlf, wkf, bk, kp);
    k_gemm_nt_f16<<<gProj, 256, F16_SMEM>>>(xhf, xlf, wvf, bv, vp);

    rmsnorm_rope<<<(NM * NH) / 8, 256>>>(rope, gq, gk);
    transpose_v_f16<<<dim3(NS / 32, NC / 32, NB), dim3(32, 8)>>>();

    k_flash<<<dim3(NS / 128, NBH), 256, FLASH_SMEM>>>();

    k_gemm_nt<<<gProj, 256, GEMM_SMEM>>>(ch, cl, woh, wol, bo, out);
}

// round 9
// speedup vs baseline: 3.0680x; 1.1130x over previous
#include <cuda_runtime.h>
#include <cuda_bf16.h>
#include <cuda_fp16.h>
#include <math.h>
#include <stdint.h>
#include <stddef.h>

#define NB 2
#define NS 2048
#define NC 2048
#define ND 128
#define NH 16
#define NM (NB * NS)       // 4096
#define NBH (NB * NH)      // 32
#define RMS_EPS 1.1920928955078125e-07f
#define SM_SCALE 0.08838834764831844f

typedef __nv_bfloat16 bf16;
typedef __half f16;

// ---------------- scratch (device globals; no allocation) ----------------
__device__ float g_q[(size_t)NM * NC];
__device__ float g_k[(size_t)NM * NC];
__device__ float g_v[(size_t)NM * NC];

// f16 operands (projections, PV value tile, ctx)
__device__ f16 g_xhf[(size_t)NM * NC], g_xlf[(size_t)NM * NC];
__device__ f16 g_wqf[(size_t)NC * NC], g_wkf[(size_t)NC * NC];
__device__ f16 g_wvf[(size_t)NC * NC], g_wof[(size_t)NC * NC];
__device__ f16 g_vtf[(size_t)NB * NC * NS];
__device__ f16 g_chf[(size_t)NM * NC], g_clf[(size_t)NM * NC];

// bf16 split operands (scores q/k only)
__device__ bf16 g_qh[(size_t)NM * NC], g_ql[(size_t)NM * NC];
__device__ bf16 g_kh[(size_t)NM * NC], g_kl[(size_t)NM * NC];

// ---------------- PTX helpers (sm_80-era, family-target safe) -------------
__device__ __forceinline__ uint32_t smem_to_u32(const void* p) {
    uint32_t a;
    asm("{ .reg .u64 t; cvta.to.shared.u64 t, %1; cvt.u32.u64 %0, t; }"
        : "=r"(a) : "l"(p));
    return a;
}
__device__ __forceinline__ void cp_async16(uint32_t dst, const void* src) {
    asm volatile("cp.async.cg.shared.global [%0], [%1], 16;"
                 :: "r"(dst), "l"(src) : "memory");
}
__device__ __forceinline__ void cp_commit() {
    asm volatile("cp.async.commit_group;" ::: "memory");
}
template <int N>
__device__ __forceinline__ void cp_wait() {
    asm volatile("cp.async.wait_group %0;" :: "n"(N) : "memory");
}
__device__ __forceinline__ void ldm_x4(uint32_t (&r)[4], uint32_t addr) {
    asm volatile("ldmatrix.sync.aligned.m8n8.x4.shared.b16 {%0,%1,%2,%3}, [%4];"
                 : "=r"(r[0]), "=r"(r[1]), "=r"(r[2]), "=r"(r[3]) : "r"(addr));
}
__device__ __forceinline__ void mma_bf16(float (&d)[4], const uint32_t (&a)[4],
                                         uint32_t b0, uint32_t b1) {
    asm volatile("mma.sync.aligned.m16n8k16.row.col.f32.bf16.bf16.f32 "
                 "{%0,%1,%2,%3}, {%4,%5,%6,%7}, {%8,%9}, {%0,%1,%2,%3};"
                 : "+f"(d[0]), "+f"(d[1]), "+f"(d[2]), "+f"(d[3])
                 : "r"(a[0]), "r"(a[1]), "r"(a[2]), "r"(a[3]), "r"(b0), "r"(b1));
}
__device__ __forceinline__ void mma_f16(float (&d)[4], const uint32_t (&a)[4],
                                        uint32_t b0, uint32_t b1) {
    asm volatile("mma.sync.aligned.m16n8k16.row.col.f32.f16.f16.f32 "
                 "{%0,%1,%2,%3}, {%4,%5,%6,%7}, {%8,%9}, {%0,%1,%2,%3};"
                 : "+f"(d[0]), "+f"(d[1]), "+f"(d[2]), "+f"(d[3])
                 : "r"(a[0]), "r"(a[1]), "r"(a[2]), "r"(a[3]), "r"(b0), "r"(b1));
}

__device__ __forceinline__ void split2(float x, bf16& h, bf16& l) {
    h = __float2bfloat16_rn(x);
    l = __float2bfloat16_rn(x - __bfloat162float(h));
}
__device__ __forceinline__ void split2f(float x, f16& h, f16& l) {
    h = __float2half_rn(x);
    l = __float2half_rn(x - __half2float(h));
}
__device__ __forceinline__ uint32_t pack_f16x2(float x, float y) {
    __half2 H = __floats2half2_rn(x, y);
    return *reinterpret_cast<uint32_t*>(&H);
}

// ---------------- common tiling constants ----------------
#define KCH 32
#define ROW_BYTES 80
#define TILE_BYTES (128 * ROW_BYTES)        // 10240

__device__ __forceinline__ void load_tile_async(uint32_t smbase, const void* g,
                                                int ld, int k0, int tid) {
    const char* gp = (const char*)g + (size_t)k0 * 2;
    #pragma unroll
    for (int j = 0; j < 2; j++) {
        int i = tid + j * 256;
        int row = i >> 2;
        int c = i & 3;
        cp_async16(smbase + row * ROW_BYTES + c * 16,
                   gp + (size_t)row * ld * 2 + c * 16);
    }
}

// =========================================================================
// f16 2-term GEMM (QKV + out-proj): A split 2xf16, B single f16
// =========================================================================
#define F16_STAGE (3 * TILE_BYTES)          // 30720
#define F16_SMEM (2 * F16_STAGE)            // 61440

__global__ __launch_bounds__(256)
void k_gemm_nt_f16(const f16* __restrict__ AhG, const f16* __restrict__ AlG,
                   const f16* __restrict__ BfG, const float* __restrict__ biasG,
                   float* __restrict__ OutG)
{
    size_t bm = (size_t)blockIdx.y * 128;
    size_t bn = (size_t)blockIdx.x * 128;
    const f16* Ah = AhG + bm * NC;
    const f16* Al = AlG + bm * NC;
    const f16* Bf = BfG + bn * NC;
    const float* bias = biasG + bn;
    float* Out = OutG + bm * NC + bn;

    extern __shared__ char sm[];
    uint32_t sb = smem_to_u32(sm);
    const int tid = threadIdx.x;
    const int lane = tid & 31;
    const int warp = tid >> 5;
    const int wm = warp >> 1;
    const int wn = warp & 1;

    float acc[2][8][4];
    #pragma unroll
    for (int mt = 0; mt < 2; mt++)
        #pragma unroll
        for (int nt = 0; nt < 8; nt++)
            #pragma unroll
            for (int j = 0; j < 4; j++) acc[mt][nt][j] = 0.0f;

    const int nch = NC / KCH;

    auto load_chunk = [&](int ch, int s) {
        uint32_t base = sb + s * F16_STAGE;
        int k0 = ch * KCH;
        load_tile_async(base,                  Ah, NC, k0, tid);
        load_tile_async(base + TILE_BYTES,     Al, NC, k0, tid);
        load_tile_async(base + 2 * TILE_BYTES, Bf, NC, k0, tid);
    };

    load_chunk(0, 0);
    cp_commit();

    for (int ch = 0; ch < nch; ch++) {
        int cur = ch & 1;
        if (ch + 1 < nch) {
            load_chunk(ch + 1, cur ^ 1);
            cp_commit();
            cp_wait<1>();
        } else {
            cp_wait<0>();
        }
        __syncthreads();

        uint32_t base = sb + cur * F16_STAGE;
        #pragma unroll
        for (int ks = 0; ks < 2; ks++) {
            uint32_t koff = (uint32_t)(ks * 32 + (lane >> 4) * 16);
            uint32_t ah[2][4], al[2][4];
            #pragma unroll
            for (int mt = 0; mt < 2; mt++) {
                uint32_t r = wm * 32 + mt * 16 + (lane & 15);
                uint32_t addr = base + r * ROW_BYTES + koff;
                ldm_x4(ah[mt], addr);
                ldm_x4(al[mt], addr + TILE_BYTES);
            }
            uint32_t bfr[4][4];
            #pragma unroll
            for (int ng = 0; ng < 4; ng++) {
                uint32_t r = wn * 64 + ng * 16 + (lane & 15);
                ldm_x4(bfr[ng], base + 2 * TILE_BYTES + r * ROW_BYTES + koff);
            }
            #pragma unroll
            for (int mt = 0; mt < 2; mt++)
                #pragma unroll
                for (int ng = 0; ng < 4; ng++) {
                    mma_f16(acc[mt][2 * ng],     ah[mt], bfr[ng][0], bfr[ng][2]);
                    mma_f16(acc[mt][2 * ng],     al[mt], bfr[ng][0], bfr[ng][2]);
                    mma_f16(acc[mt][2 * ng + 1], ah[mt], bfr[ng][1], bfr[ng][3]);
                    mma_f16(acc[mt][2 * ng + 1], al[mt], bfr[ng][1], bfr[ng][3]);
                }
        }
        __syncthreads();
    }

    #pragma unroll
    for (int mt = 0; mt < 2; mt++) {
        int r0 = wm * 32 + mt * 16 + (lane >> 2);
        #pragma unroll
        for (int nt = 0; nt < 8; nt++) {
            int c = wn * 64 + nt * 8 + (lane & 3) * 2;
            float bx = bias[c], by = bias[c + 1];
            float2 v0 = { acc[mt][nt][0] + bx, acc[mt][nt][1] + by };
            float2 v1 = { acc[mt][nt][2] + bx, acc[mt][nt][3] + by };
            *(float2*)(Out + (size_t)r0 * NC + c) = v0;
            *(float2*)(Out + (size_t)(r0 + 8) * NC + c) = v1;
        }
    }
}

// =========================================================================
// Flash attention: scores (bf16x3) + online softmax + PV (single f16 P<=1)
// =========================================================================
#define FT_ROWB 272                          // 256B row + 16B pad
#define FT_TILE (128 * FT_ROWB)              // 34816
#define OFF_KH 0
#define OFF_KL FT_TILE
#define OFF_VF (2 * FT_TILE)
#define FLASH_SMEM (3 * FT_TILE)             // 104448

__device__ __forceinline__ void fa_load_pair(uint32_t dsthi, uint32_t dstlo,
                                             const bf16* gh, const bf16* gl,
                                             size_t rowbase, size_t ldrow, int tid)
{
    #pragma unroll
    for (int i = 0; i < 8; i++) {
        int idx = tid + i * 256;
        int row = idx >> 4;
        int ch = idx & 15;
        const char* ph = (const char*)(gh + rowbase + (size_t)row * ldrow) + ch * 16;
        const char* pl = (const char*)(gl + rowbase + (size_t)row * ldrow) + ch * 16;
        cp_async16(dsthi + row * FT_ROWB + ch * 16, ph);
        cp_async16(dstlo + row * FT_ROWB + ch * 16, pl);
    }
}
__device__ __forceinline__ void fa_load_one(uint32_t dst, const f16* g,
                                            size_t rowbase, size_t ldrow, int tid)
{
    #pragma unroll
    for (int i = 0; i < 8; i++) {
        int idx = tid + i * 256;
        int row = idx >> 4;
        int ch = idx & 15;
        cp_async16(dst + row * FT_ROWB + ch * 16,
                   (const char*)(g + rowbase + (size_t)row * ldrow) + ch * 16);
    }
}

__global__ void __launch_bounds__(256, 1) k_flash()
{
    extern __shared__ char sm[];
    uint32_t sb = smem_to_u32(sm);
    const int tid = threadIdx.x;
    const int lane = tid & 31;
    const int warp = tid >> 5;
    const int q0 = blockIdx.x * 128;
    const int bh = blockIdx.y, b = bh >> 4, h = bh & 15;

    // ---- load Q tile (hi/lo) into K buffer, move to register fragments ----
    fa_load_pair(sb + OFF_KH, sb + OFF_KL, g_qh, g_ql,
                 (size_t)(b * NS + q0) * NC + (size_t)h * ND, NC, tid);
    cp_commit();
    cp_wait<0>();
    __syncthreads();

    uint32_t qhf[8][4], qlf[8][4];
    {
        uint32_t rbase = sb + (warp * 16 + (lane & 15)) * FT_ROWB + ((lane >> 4) << 4);
        #pragma unroll
        for (int ks = 0; ks < 8; ks++) {
            ldm_x4(qhf[ks], rbase + OFF_KH + ks * 32);
            ldm_x4(qlf[ks], rbase + OFF_KL + ks * 32);
        }
    }
    __syncthreads();

    // ---- prime pipeline: K0 then V0 (separate commit groups) ----
    fa_load_pair(sb + OFF_KH, sb + OFF_KL, g_kh, g_kl,
                 (size_t)(b * NS) * NC + (size_t)h * ND, NC, tid);
    cp_commit();
    fa_load_one(sb + OFF_VF, g_vtf,
                ((size_t)b * NC + (size_t)h * ND) * NS, NS, tid);
    cp_commit();

    float o[16][4];
    #pragma unroll
    for (int i = 0; i < 16; i++) { o[i][0] = 0.f; o[i][1] = 0.f; o[i][2] = 0.f; o[i][3] = 0.f; }
    float m0 = -1e30f, m1 = -1e30f, l0 = 0.f, l1 = 0.f;

    for (int j = 0; j < 16; j++) {
        // (A) K_j ready
        cp_wait<1>();
        __syncthreads();

        // (B) S = Q @ K_j^T  (bf16x3)
        float s[16][4];
        #pragma unroll
        for (int i = 0; i < 16; i++) { s[i][0] = 0.f; s[i][1] = 0.f; s[i][2] = 0.f; s[i][3] = 0.f; }
        #pragma unroll
        for (int ng = 0; ng < 8; ng++) {
            #pragma unroll
            for (int ks = 0; ks < 8; ks++) {
                uint32_t addr = sb + (ng * 16 + (lane & 15)) * FT_ROWB
                              + ((lane >> 4) << 4) + ks * 32;
                uint32_t bh4[4], bl4[4];
                ldm_x4(bh4, addr + OFF_KH);
                ldm_x4(bl4, addr + OFF_KL);
                mma_bf16(s[2 * ng],     qhf[ks], bh4[0], bh4[2]);
                mma_bf16(s[2 * ng],     qhf[ks], bl4[0], bl4[2]);
                mma_bf16(s[2 * ng],     qlf[ks], bh4[0], bh4[2]);
                mma_bf16(s[2 * ng + 1], qhf[ks], bh4[1], bh4[3]);
                mma_bf16(s[2 * ng + 1], qhf[ks], bl4[1], bl4[3]);
                mma_bf16(s[2 * ng + 1], qlf[ks], bh4[1], bh4[3]);
            }
        }
        // (C) Kbuf free -> start K_{j+1}
        __syncthreads();
        if (j + 1 < 16) {
            fa_load_pair(sb + OFF_KH, sb + OFF_KL, g_kh, g_kl,
                         (size_t)(b * NS + (j + 1) * 128) * NC + (size_t)h * ND, NC, tid);
            cp_commit();
        }

        // (D) online softmax: p = exp((s - m)*scale) <= 1 (f16-safe by construction)
        float mx0 = -1e30f, mx1 = -1e30f;
        #pragma unroll
        for (int i = 0; i < 16; i++) {
            mx0 = fmaxf(mx0, fmaxf(s[i][0], s[i][1]));
            mx1 = fmaxf(mx1, fmaxf(s[i][2], s[i][3]));
        }
        mx0 = fmaxf(mx0, __shfl_xor_sync(0xffffffffu, mx0, 1));
        mx0 = fmaxf(mx0, __shfl_xor_sync(0xffffffffu, mx0, 2));
        mx1 = fmaxf(mx1, __shfl_xor_sync(0xffffffffu, mx1, 1));
        mx1 = fmaxf(mx1, __shfl_xor_sync(0xffffffffu, mx1, 2));
        float nm0 = fmaxf(m0, mx0), nm1 = fmaxf(m1, mx1);
        float a0 = __expf((m0 - nm0) * SM_SCALE);
        float a1 = __expf((m1 - nm1) * SM_SCALE);
        m0 = nm0; m1 = nm1;
        float ps0 = 0.f, ps1 = 0.f;
        #pragma unroll
        for (int i = 0; i < 16; i++) {
            s[i][0] = __expf((s[i][0] - m0) * SM_SCALE);
            s[i][1] = __expf((s[i][1] - m0) * SM_SCALE);
            s[i][2] = __expf((s[i][2] - m1) * SM_SCALE);
            s[i][3] = __expf((s[i][3] - m1) * SM_SCALE);
            ps0 += s[i][0] + s[i][1];
            ps1 += s[i][2] + s[i][3];
        }
        l0 = l0 * a0 + ps0;
        l1 = l1 * a1 + ps1;
        #pragma unroll
        for (int i = 0; i < 16; i++) {
            o[i][0] *= a0; o[i][1] *= a0; o[i][2] *= a1; o[i][3] *= a1;
        }

        // (E) V_j ready
        if (j + 1 < 16) cp_wait<1>(); else cp_wait<0>();
        __syncthreads();

        // (F) ctx += P @ V_j  (P single f16 in [0,1], V single f16)
        #pragma unroll
        for (int ks = 0; ks < 8; ks++) {
            uint32_t pa[4];
            pa[0] = pack_f16x2(s[2 * ks][0],     s[2 * ks][1]);
            pa[1] = pack_f16x2(s[2 * ks][2],     s[2 * ks][3]);
            pa[2] = pack_f16x2(s[2 * ks + 1][0], s[2 * ks + 1][1]);
            pa[3] = pack_f16x2(s[2 * ks + 1][2], s[2 * ks + 1][3]);
            #pragma unroll
            for (int ng = 0; ng < 8; ng++) {
                uint32_t addr = sb + OFF_VF + (ng * 16 + (lane & 15)) * FT_ROWB
                              + ((lane >> 4) << 4) + ks * 32;
                uint32_t vf4[4];
                ldm_x4(vf4, addr);
                mma_f16(o[2 * ng],     pa, vf4[0], vf4[2]);
                mma_f16(o[2 * ng + 1], pa, vf4[1], vf4[3]);
            }
        }
        // (G) Vbuf free -> start V_{j+1}
        __syncthreads();
        if (j + 1 < 16) {
            fa_load_one(sb + OFF_VF, g_vtf,
                        ((size_t)b * NC + (size_t)h * ND) * NS + (j + 1) * 128, NS, tid);
            cp_commit();
        }
    }

    // ---- finalize: normalize, split to f16 hi/lo, write ctx ----
    l0 += __shfl_xor_sync(0xffffffffu, l0, 1);
    l0 += __shfl_xor_sync(0xffffffffu, l0, 2);
    l1 += __shfl_xor_sync(0xffffffffu, l1, 1);
    l1 += __shfl_xor_sync(0xffffffffu, l1, 2);
    float i0 = 1.0f / l0, i1 = 1.0f / l1;

    size_t gr0 = (size_t)(b * NS + q0 + warp * 16 + (lane >> 2));
    #pragma unroll
    for (int nt = 0; nt < 16; nt++) {
        int c = h * ND + nt * 8 + (lane & 3) * 2;
        f16 h0, h1, lo0, lo1;
        split2f(o[nt][0] * i0, h0, lo0);
        split2f(o[nt][1] * i0, h1, lo1);
        *(__half2*)(g_chf + gr0 * NC + c) = __half2{h0, h1};
        *(__half2*)(g_clf + gr0 * NC + c) = __half2{lo0, lo1};
        split2f(o[nt][2] * i1, h0, lo0);
        split2f(o[nt][3] * i1, h1, lo1);
        *(__half2*)(g_chf + (gr0 + 8) * NC + c) = __half2{h0, h1};
        *(__half2*)(g_clf + (gr0 + 8) * NC + c) = __half2{lo0, lo1};
    }
}

// ---------------- elementwise kernels ----------------
__global__ __launch_bounds__(256) void cvt_split_f16(const float* __restrict__ src,
                                                     f16* __restrict__ hi,
                                                     f16* __restrict__ lo)
{
    size_t i = (size_t)blockIdx.x * 256 + threadIdx.x;
    float4 v = ((const float4*)src)[i];
    f16 h0, h1, h2, h3, l0, l1, l2, l3;
    split2f(v.x, h0, l0); split2f(v.y, h1, l1);
    split2f(v.z, h2, l2); split2f(v.w, h3, l3);
    __half2* hp = (__half2*)hi;
    __half2* lp = (__half2*)lo;
    hp[2 * i]     = __half2{h0, h1};
    hp[2 * i + 1] = __half2{h2, h3};
    lp[2 * i]     = __half2{l0, l1};
    lp[2 * i + 1] = __half2{l2, l3};
}

__global__ __launch_bounds__(256) void cvt_f16(const float* __restrict__ src,
                                               f16* __restrict__ dst)
{
    size_t i = (size_t)blockIdx.x * 256 + threadIdx.x;
    float4 v = ((const float4*)src)[i];
    __half2* dp = (__half2*)dst;
    dp[2 * i]     = __floats2half2_rn(v.x, v.y);
    dp[2 * i + 1] = __floats2half2_rn(v.z, v.w);
}

// V transpose to single f16: g_v[(b*S+s), c] -> vT[(b*C+c), s]
__global__ __launch_bounds__(256) void transpose_v_f16()
{
    __shared__ float t[32][33];
    int b = blockIdx.z;
    int s0 = blockIdx.x * 32, c0 = blockIdx.y * 32;
    int tx = threadIdx.x, ty = threadIdx.y;  // 32 x 8
    #pragma unroll
    for (int j = 0; j < 4; j++) {
        int s = s0 + ty + j * 8;
        t[ty + j * 8][tx] = g_v[((size_t)b * NS + s) * NC + c0 + tx];
    }
    __syncthreads();
    #pragma unroll
    for (int j = 0; j < 4; j++) {
        int c = c0 + ty + j * 8;
        g_vtf[((size_t)b * NC + c) * NS + s0 + tx] = __float2half_rn(t[tx][ty + j * 8]);
    }
}

// Per-head RMSNorm + RoPE; reads fp32 g_q/g_k, writes split bf16 qh/ql/kh/kl.
__global__ __launch_bounds__(256) void rmsnorm_rope(
    const float* __restrict__ rope,
    const float* __restrict__ gq, const float* __restrict__ gk)
{
    int warp = blockIdx.x * 8 + (threadIdx.x >> 5);
    int lane = threadIdx.x & 31;
    int m = warp >> 4;
    int h = warp & 15;
    int s = m & (NS - 1);

    size_t off = (size_t)m * NC + h * ND;
    const float* qr = g_q + off;
    const float* kr = g_k + off;
    const float* rp = rope + (size_t)s * (ND / 2) * 4;
    int d = lane * 4;

    float4 xq = *(const float4*)(qr + d);
    float4 xk = *(const float4*)(kr + d);
    float ssq = xq.x * xq.x + xq.y * xq.y + xq.z * xq.z + xq.w * xq.w;
    float ssk = xk.x * xk.x + xk.y * xk.y + xk.z * xk.z + xk.w * xk.w;
    #pragma unroll
    for (int o = 16; o; o >>= 1) {
        ssq += __shfl_xor_sync(0xffffffffu, ssq, o);
        ssk += __shfl_xor_sync(0xffffffffu, ssk, o);
    }
    float rq = rsqrtf(ssq * (1.0f / ND) + RMS_EPS);
    float rk = rsqrtf(ssk * (1.0f / ND) + RMS_EPS);

    float4 gqv = *(const float4*)(gq + d);
    float4 gkv = *(const float4*)(gk + d);
    xq.x *= rq * gqv.x; xq.y *= rq * gqv.y; xq.z *= rq * gqv.z; xq.w *= rq * gqv.w;
    xk.x *= rk * gkv.x; xk.y *= rk * gkv.y; xk.z *= rk * gkv.z; xk.w *= rk * gkv.w;

    float4 r0 = *(const float4*)(rp + (size_t)(2 * lane) * 4);
    float4 r1 = *(const float4*)(rp + (size_t)(2 * lane + 1) * 4);
    float4 oq, ok;
    oq.x = r0.x * xq.x + r0.y * xq.y;  oq.y = r0.z * xq.x + r0.w * xq.y;
    oq.z = r1.x * xq.z + r1.y * xq.w;  oq.w = r1.z * xq.z + r1.w * xq.w;
    ok.x = r0.x * xk.x + r0.y * xk.y;  ok.y = r0.z * xk.x + r0.w * xk.y;
    ok.z = r1.x * xk.z + r1.y * xk.w;  ok.w = r1.z * xk.z + r1.w * xk.w;

    bf16 h0, h1, h2, h3, l0, l1, l2, l3;
    split2(oq.x, h0, l0); split2(oq.y, h1, l1);
    split2(oq.z, h2, l2); split2(oq.w, h3, l3);
    *(__nv_bfloat162*)(g_qh + off + d)     = __nv_bfloat162{h0, h1};
    *(__nv_bfloat162*)(g_qh + off + d + 2) = __nv_bfloat162{h2, h3};
    *(__nv_bfloat162*)(g_ql + off + d)     = __nv_bfloat162{l0, l1};
    *(__nv_bfloat162*)(g_ql + off + d + 2) = __nv_bfloat162{l2, l3};

    split2(ok.x, h0, l0); split2(ok.y, h1, l1);
    split2(ok.z, h2, l2); split2(ok.w, h3, l3);
    *(__nv_bfloat162*)(g_kh + off + d)     = __nv_bfloat162{h0, h1};
    *(__nv_bfloat162*)(g_kh + off + d + 2) = __nv_bfloat162{h2, h3};
    *(__nv_bfloat162*)(g_kl + off + d)     = __nv_bfloat162{l0, l1};
    *(__nv_bfloat162*)(g_kl + off + d + 2) = __nv_bfloat162{l2, l3};
}

// ---------------- launch ----------------
extern "C" void kernel_launch(void* const* d_in, const int* in_sizes, int n_in,
                              void* d_out, int out_size)
{
    const float* x    = (const float*)d_in[0];
    const float* rope = (const float*)d_in[1];
    const float* Wq   = (const float*)d_in[2];
    const float* bq   = (const float*)d_in[3];
    const float* Wk   = (const float*)d_in[4];
    const float* bk   = (const float*)d_in[5];
    const float* Wv   = (const float*)d_in[6];
    const float* bv   = (const float*)d_in[7];
    const float* gq   = (const float*)d_in[8];
    const float* gk   = (const float*)d_in[9];
    const float* Wo   = (const float*)d_in[10];
    const float* bo   = (const float*)d_in[11];
    float* out = (float*)d_out;

    cudaFuncSetAttribute(k_gemm_nt_f16, cudaFuncAttributeMaxDynamicSharedMemorySize, F16_SMEM);
    cudaFuncSetAttribute(k_flash, cudaFuncAttributeMaxDynamicSharedMemorySize, FLASH_SMEM);

    float *qp, *kp, *vp;
    f16 *xhf, *xlf, *wqf, *wkf, *wvf, *wof, *chf, *clf;
    cudaGetSymbolAddress((void**)&qp, g_q);
    cudaGetSymbolAddress((void**)&kp, g_k);
    cudaGetSymbolAddress((void**)&vp, g_v);
    cudaGetSymbolAddress((void**)&xhf, g_xhf); cudaGetSymbolAddress((void**)&xlf, g_xlf);
    cudaGetSymbolAddress((void**)&wqf, g_wqf); cudaGetSymbolAddress((void**)&wkf, g_wkf);
    cudaGetSymbolAddress((void**)&wvf, g_wvf); cudaGetSymbolAddress((void**)&wof, g_wof);
    cudaGetSymbolAddress((void**)&chf, g_chf); cudaGetSymbolAddress((void**)&clf, g_clf);

    const size_t nX = (size_t)NM * NC;       // 8M elems
    const size_t nW = (size_t)NC * NC;       // 4M elems

    cvt_split_f16<<<(unsigned)(nX / 1024), 256>>>(x, xhf, xlf);
    cvt_f16<<<(unsigned)(nW / 1024), 256>>>(Wq, wqf);
    cvt_f16<<<(unsigned)(nW / 1024), 256>>>(Wk, wkf);
    cvt_f16<<<(unsigned)(nW / 1024), 256>>>(Wv, wvf);
    cvt_f16<<<(unsigned)(nW / 1024), 256>>>(Wo, wof);

    dim3 gProj(NC / 128, NM / 128);          // (16, 32)
    k_gemm_nt_f16<<<gProj, 256, F16_SMEM>>>(xhf, xlf, wqf, bq, qp);
    k_gemm_nt_f16<<<gProj, 256, F16_SMEM>>>(xhf, xlf, wkf, bk, kp);
    k_gemm_nt_f16<<<gProj, 256, F16_SMEM>>>(xhf, xlf, wvf, bv, vp);

    rmsnorm_rope<<<(NM * NH) / 8, 256>>>(rope, gq, gk);
    transpose_v_f16<<<dim3(NS / 32, NC / 32, NB), dim3(32, 8)>>>();

    k_flash<<<dim3(NS / 128, NBH), 256, FLASH_SMEM>>>();

    k_gemm_nt_f16<<<gProj, 256, F16_SMEM>>>(chf, clf, wof, bo, out);
}

// round 10
// speedup vs baseline: 3.3091x; 1.0786x over previous
#include <cuda_runtime.h>
#include <cuda_bf16.h>
#include <cuda_fp16.h>
#include <math.h>
#include <stdint.h>
#include <stddef.h>

#define NB 2
#define NS 2048
#define NC 2048
#define ND 128
#define NH 16
#define NM (NB * NS)       // 4096
#define NBH (NB * NH)      // 32
#define RMS_EPS 1.1920928955078125e-07f
#define SM_SCALE 0.08838834764831844f

typedef __half f16;

// ---------------- scratch (device globals; no allocation) ----------------
__device__ float g_q[(size_t)NM * NC];
__device__ float g_k[(size_t)NM * NC];
__device__ float g_v[(size_t)NM * NC];

// f16 operands
__device__ f16 g_xhf[(size_t)NM * NC], g_xlf[(size_t)NM * NC];
__device__ f16 g_wqf[(size_t)NC * NC], g_wkf[(size_t)NC * NC];
__device__ f16 g_wvf[(size_t)NC * NC], g_wof[(size_t)NC * NC];
__device__ f16 g_vtf[(size_t)NB * NC * NS];
__device__ f16 g_chf[(size_t)NM * NC], g_clf[(size_t)NM * NC];
__device__ f16 g_qhf[(size_t)NM * NC], g_qlf[(size_t)NM * NC];   // Q split 2xf16
__device__ f16 g_kf[(size_t)NM * NC];                            // K single f16

// ---------------- PTX helpers (sm_80-era, family-target safe) -------------
__device__ __forceinline__ uint32_t smem_to_u32(const void* p) {
    uint32_t a;
    asm("{ .reg .u64 t; cvta.to.shared.u64 t, %1; cvt.u32.u64 %0, t; }"
        : "=r"(a) : "l"(p));
    return a;
}
__device__ __forceinline__ void cp_async16(uint32_t dst, const void* src) {
    asm volatile("cp.async.cg.shared.global [%0], [%1], 16;"
                 :: "r"(dst), "l"(src) : "memory");
}
__device__ __forceinline__ void cp_commit() {
    asm volatile("cp.async.commit_group;" ::: "memory");
}
template <int N>
__device__ __forceinline__ void cp_wait() {
    asm volatile("cp.async.wait_group %0;" :: "n"(N) : "memory");
}
__device__ __forceinline__ void ldm_x4(uint32_t (&r)[4], uint32_t addr) {
    asm volatile("ldmatrix.sync.aligned.m8n8.x4.shared.b16 {%0,%1,%2,%3}, [%4];"
                 : "=r"(r[0]), "=r"(r[1]), "=r"(r[2]), "=r"(r[3]) : "r"(addr));
}
__device__ __forceinline__ void mma_f16(float (&d)[4], const uint32_t (&a)[4],
                                        uint32_t b0, uint32_t b1) {
    asm volatile("mma.sync.aligned.m16n8k16.row.col.f32.f16.f16.f32 "
                 "{%0,%1,%2,%3}, {%4,%5,%6,%7}, {%8,%9}, {%0,%1,%2,%3};"
                 : "+f"(d[0]), "+f"(d[1]), "+f"(d[2]), "+f"(d[3])
                 : "r"(a[0]), "r"(a[1]), "r"(a[2]), "r"(a[3]), "r"(b0), "r"(b1));
}

__device__ __forceinline__ void split2f(float x, f16& h, f16& l) {
    h = __float2half_rn(x);
    l = __float2half_rn(x - __half2float(h));
}
__device__ __forceinline__ uint32_t pack_f16x2(float x, float y) {
    __half2 H = __floats2half2_rn(x, y);
    return *reinterpret_cast<uint32_t*>(&H);
}

// ---------------- common tiling constants ----------------
#define KCH 32
#define ROW_BYTES 80
#define TILE_BYTES (128 * ROW_BYTES)        // 10240

__device__ __forceinline__ void load_tile_async(uint32_t smbase, const void* g,
                                                int ld, int k0, int tid) {
    const char* gp = (const char*)g + (size_t)k0 * 2;
    #pragma unroll
    for (int j = 0; j < 2; j++) {
        int i = tid + j * 256;
        int row = i >> 2;
        int c = i & 3;
        cp_async16(smbase + row * ROW_BYTES + c * 16,
                   gp + (size_t)row * ld * 2 + c * 16);
    }
}

// =========================================================================
// f16 2-term GEMM (QKV + out-proj): A split 2xf16, B single f16
// =========================================================================
#define F16_STAGE (3 * TILE_BYTES)          // 30720
#define F16_SMEM (2 * F16_STAGE)            // 61440

__global__ __launch_bounds__(256)
void k_gemm_nt_f16(const f16* __restrict__ AhG, const f16* __restrict__ AlG,
                   const f16* __restrict__ BfG, const float* __restrict__ biasG,
                   float* __restrict__ OutG)
{
    size_t bm = (size_t)blockIdx.y * 128;
    size_t bn = (size_t)blockIdx.x * 128;
    const f16* Ah = AhG + bm * NC;
    const f16* Al = AlG + bm * NC;
    const f16* Bf = BfG + bn * NC;
    const float* bias = biasG + bn;
    float* Out = OutG + bm * NC + bn;

    extern __shared__ char sm[];
    uint32_t sb = smem_to_u32(sm);
    const int tid = threadIdx.x;
    const int lane = tid & 31;
    const int warp = tid >> 5;
    const int wm = warp >> 1;
    const int wn = warp & 1;

    float acc[2][8][4];
    #pragma unroll
    for (int mt = 0; mt < 2; mt++)
        #pragma unroll
        for (int nt = 0; nt < 8; nt++)
            #pragma unroll
            for (int j = 0; j < 4; j++) acc[mt][nt][j] = 0.0f;

    const int nch = NC / KCH;

    auto load_chunk = [&](int ch, int s) {
        uint32_t base = sb + s * F16_STAGE;
        int k0 = ch * KCH;
        load_tile_async(base,                  Ah, NC, k0, tid);
        load_tile_async(base + TILE_BYTES,     Al, NC, k0, tid);
        load_tile_async(base + 2 * TILE_BYTES, Bf, NC, k0, tid);
    };

    load_chunk(0, 0);
    cp_commit();

    for (int ch = 0; ch < nch; ch++) {
        int cur = ch & 1;
        if (ch + 1 < nch) {
            load_chunk(ch + 1, cur ^ 1);
            cp_commit();
            cp_wait<1>();
        } else {
            cp_wait<0>();
        }
        __syncthreads();

        uint32_t base = sb + cur * F16_STAGE;
        #pragma unroll
        for (int ks = 0; ks < 2; ks++) {
            uint32_t koff = (uint32_t)(ks * 32 + (lane >> 4) * 16);
            uint32_t ah[2][4], al[2][4];
            #pragma unroll
            for (int mt = 0; mt < 2; mt++) {
                uint32_t r = wm * 32 + mt * 16 + (lane & 15);
                uint32_t addr = base + r * ROW_BYTES + koff;
                ldm_x4(ah[mt], addr);
                ldm_x4(al[mt], addr + TILE_BYTES);
            }
            uint32_t bfr[4][4];
            #pragma unroll
            for (int ng = 0; ng < 4; ng++) {
                uint32_t r = wn * 64 + ng * 16 + (lane & 15);
                ldm_x4(bfr[ng], base + 2 * TILE_BYTES + r * ROW_BYTES + koff);
            }
            #pragma unroll
            for (int mt = 0; mt < 2; mt++)
                #pragma unroll
                for (int ng = 0; ng < 4; ng++) {
                    mma_f16(acc[mt][2 * ng],     ah[mt], bfr[ng][0], bfr[ng][2]);
                    mma_f16(acc[mt][2 * ng],     al[mt], bfr[ng][0], bfr[ng][2]);
                    mma_f16(acc[mt][2 * ng + 1], ah[mt], bfr[ng][1], bfr[ng][3]);
                    mma_f16(acc[mt][2 * ng + 1], al[mt], bfr[ng][1], bfr[ng][3]);
                }
        }
        __syncthreads();
    }

    #pragma unroll
    for (int mt = 0; mt < 2; mt++) {
        int r0 = wm * 32 + mt * 16 + (lane >> 2);
        #pragma unroll
        for (int nt = 0; nt < 8; nt++) {
            int c = wn * 64 + nt * 8 + (lane & 3) * 2;
            float bx = bias[c], by = bias[c + 1];
            float2 v0 = { acc[mt][nt][0] + bx, acc[mt][nt][1] + by };
            float2 v1 = { acc[mt][nt][2] + bx, acc[mt][nt][3] + by };
            *(float2*)(Out + (size_t)r0 * NC + c) = v0;
            *(float2*)(Out + (size_t)(r0 + 8) * NC + c) = v1;
        }
    }
}

// =========================================================================
// Flash attention: scores (f16 2-term) + online softmax + PV (f16 1-term)
// =========================================================================
#define FT_ROWB 272                          // 256B row + 16B pad
#define FT_TILE (128 * FT_ROWB)              // 34816
#define OFF_KF 0
#define OFF_VF FT_TILE
#define FLASH_SMEM (2 * FT_TILE)             // 69632

__device__ __forceinline__ void fa_load_one(uint32_t dst, const f16* g,
                                            size_t rowbase, size_t ldrow, int tid)
{
    #pragma unroll
    for (int i = 0; i < 8; i++) {
        int idx = tid + i * 256;
        int row = idx >> 4;
        int ch = idx & 15;
        cp_async16(dst + row * FT_ROWB + ch * 16,
                   (const char*)(g + rowbase + (size_t)row * ldrow) + ch * 16);
    }
}

__global__ void __launch_bounds__(256, 1) k_flash()
{
    extern __shared__ char sm[];
    uint32_t sb = smem_to_u32(sm);
    const int tid = threadIdx.x;
    const int lane = tid & 31;
    const int warp = tid >> 5;
    const int q0 = blockIdx.x * 128;
    const int bh = blockIdx.y, b = bh >> 4, h = bh & 15;

    // ---- stage Q hi/lo through the two smem buffers, move to registers ----
    size_t qbase = (size_t)(b * NS + q0) * NC + (size_t)h * ND;
    fa_load_one(sb + OFF_KF, g_qhf, qbase, NC, tid);
    fa_load_one(sb + OFF_VF, g_qlf, qbase, NC, tid);
    cp_commit();
    cp_wait<0>();
    __syncthreads();

    uint32_t qhf[8][4], qlf[8][4];
    {
        uint32_t rbase = sb + (warp * 16 + (lane & 15)) * FT_ROWB + ((lane >> 4) << 4);
        #pragma unroll
        for (int ks = 0; ks < 8; ks++) {
            ldm_x4(qhf[ks], rbase + OFF_KF + ks * 32);
            ldm_x4(qlf[ks], rbase + OFF_VF + ks * 32);
        }
    }
    __syncthreads();

    // ---- prime pipeline: K0 then V0 (separate commit groups) ----
    fa_load_one(sb + OFF_KF, g_kf, (size_t)(b * NS) * NC + (size_t)h * ND, NC, tid);
    cp_commit();
    fa_load_one(sb + OFF_VF, g_vtf, ((size_t)b * NC + (size_t)h * ND) * NS, NS, tid);
    cp_commit();

    float o[16][4];
    #pragma unroll
    for (int i = 0; i < 16; i++) { o[i][0] = 0.f; o[i][1] = 0.f; o[i][2] = 0.f; o[i][3] = 0.f; }
    float m0 = -1e30f, m1 = -1e30f, l0 = 0.f, l1 = 0.f;

    for (int j = 0; j < 16; j++) {
        // (A) K_j ready
        cp_wait<1>();
        __syncthreads();

        // (B) S = Q @ K_j^T  (f16 2-term: Qh*K + Ql*K)
        float s[16][4];
        #pragma unroll
        for (int i = 0; i < 16; i++) { s[i][0] = 0.f; s[i][1] = 0.f; s[i][2] = 0.f; s[i][3] = 0.f; }
        #pragma unroll
        for (int ng = 0; ng < 8; ng++) {
            #pragma unroll
            for (int ks = 0; ks < 8; ks++) {
                uint32_t addr = sb + OFF_KF + (ng * 16 + (lane & 15)) * FT_ROWB
                              + ((lane >> 4) << 4) + ks * 32;
                uint32_t kf4[4];
                ldm_x4(kf4, addr);
                mma_f16(s[2 * ng],     qhf[ks], kf4[0], kf4[2]);
                mma_f16(s[2 * ng],     qlf[ks], kf4[0], kf4[2]);
                mma_f16(s[2 * ng + 1], qhf[ks], kf4[1], kf4[3]);
                mma_f16(s[2 * ng + 1], qlf[ks], kf4[1], kf4[3]);
            }
        }
        // (C) Kbuf free -> start K_{j+1}
        __syncthreads();
        if (j + 1 < 16) {
            fa_load_one(sb + OFF_KF, g_kf,
                        (size_t)(b * NS + (j + 1) * 128) * NC + (size_t)h * ND, NC, tid);
            cp_commit();
        }

        // (D) online softmax: p = exp((s - m)*scale) <= 1 (f16-safe by construction)
        float mx0 = -1e30f, mx1 = -1e30f;
        #pragma unroll
        for (int i = 0; i < 16; i++) {
            mx0 = fmaxf(mx0, fmaxf(s[i][0], s[i][1]));
            mx1 = fmaxf(mx1, fmaxf(s[i][2], s[i][3]));
        }
        mx0 = fmaxf(mx0, __shfl_xor_sync(0xffffffffu, mx0, 1));
        mx0 = fmaxf(mx0, __shfl_xor_sync(0xffffffffu, mx0, 2));
        mx1 = fmaxf(mx1, __shfl_xor_sync(0xffffffffu, mx1, 1));
        mx1 = fmaxf(mx1, __shfl_xor_sync(0xffffffffu, mx1, 2));
        float nm0 = fmaxf(m0, mx0), nm1 = fmaxf(m1, mx1);
        float a0 = __expf((m0 - nm0) * SM_SCALE);
        float a1 = __expf((m1 - nm1) * SM_SCALE);
        m0 = nm0; m1 = nm1;
        float ps0 = 0.f, ps1 = 0.f;
        #pragma unroll
        for (int i = 0; i < 16; i++) {
            s[i][0] = __expf((s[i][0] - m0) * SM_SCALE);
            s[i][1] = __expf((s[i][1] - m0) * SM_SCALE);
            s[i][2] = __expf((s[i][2] - m1) * SM_SCALE);
            s[i][3] = __expf((s[i][3] - m1) * SM_SCALE);
            ps0 += s[i][0] + s[i][1];
            ps1 += s[i][2] + s[i][3];
        }
        l0 = l0 * a0 + ps0;
        l1 = l1 * a1 + ps1;
        #pragma unroll
        for (int i = 0; i < 16; i++) {
            o[i][0] *= a0; o[i][1] *= a0; o[i][2] *= a1; o[i][3] *= a1;
        }

        // (E) V_j ready
        if (j + 1 < 16) cp_wait<1>(); else cp_wait<0>();
        __syncthreads();

        // (F) ctx += P @ V_j  (P single f16 in [0,1], V single f16)
        #pragma unroll
        for (int ks = 0; ks < 8; ks++) {
            uint32_t pa[4];
            pa[0] = pack_f16x2(s[2 * ks][0],     s[2 * ks][1]);
            pa[1] = pack_f16x2(s[2 * ks][2],     s[2 * ks][3]);
            pa[2] = pack_f16x2(s[2 * ks + 1][0], s[2 * ks + 1][1]);
            pa[3] = pack_f16x2(s[2 * ks + 1][2], s[2 * ks + 1][3]);
            #pragma unroll
            for (int ng = 0; ng < 8; ng++) {
                uint32_t addr = sb + OFF_VF + (ng * 16 + (lane & 15)) * FT_ROWB
                              + ((lane >> 4) << 4) + ks * 32;
                uint32_t vf4[4];
                ldm_x4(vf4, addr);
                mma_f16(o[2 * ng],     pa, vf4[0], vf4[2]);
                mma_f16(o[2 * ng + 1], pa, vf4[1], vf4[3]);
            }
        }
        // (G) Vbuf free -> start V_{j+1}
        __syncthreads();
        if (j + 1 < 16) {
            fa_load_one(sb + OFF_VF, g_vtf,
                        ((size_t)b * NC + (size_t)h * ND) * NS + (j + 1) * 128, NS, tid);
            cp_commit();
        }
    }

    // ---- finalize: normalize, split to f16 hi/lo, write ctx ----
    l0 += __shfl_xor_sync(0xffffffffu, l0, 1);
    l0 += __shfl_xor_sync(0xffffffffu, l0, 2);
    l1 += __shfl_xor_sync(0xffffffffu, l1, 1);
    l1 += __shfl_xor_sync(0xffffffffu, l1, 2);
    float i0 = 1.0f / l0, i1 = 1.0f / l1;

    size_t gr0 = (size_t)(b * NS + q0 + warp * 16 + (lane >> 2));
    #pragma unroll
    for (int nt = 0; nt < 16; nt++) {
        int c = h * ND + nt * 8 + (lane & 3) * 2;
        f16 h0, h1, lo0, lo1;
        split2f(o[nt][0] * i0, h0, lo0);
        split2f(o[nt][1] * i0, h1, lo1);
        *(__half2*)(g_chf + gr0 * NC + c) = __half2{h0, h1};
        *(__half2*)(g_clf + gr0 * NC + c) = __half2{lo0, lo1};
        split2f(o[nt][2] * i1, h0, lo0);
        split2f(o[nt][3] * i1, h1, lo1);
        *(__half2*)(g_chf + (gr0 + 8) * NC + c) = __half2{h0, h1};
        *(__half2*)(g_clf + (gr0 + 8) * NC + c) = __half2{lo0, lo1};
    }
}

// ---------------- elementwise kernels ----------------
__global__ __launch_bounds__(256) void cvt_split_f16(const float* __restrict__ src,
                                                     f16* __restrict__ hi,
                                                     f16* __restrict__ lo)
{
    size_t i = (size_t)blockIdx.x * 256 + threadIdx.x;
    float4 v = ((const float4*)src)[i];
    f16 h0, h1, h2, h3, l0, l1, l2, l3;
    split2f(v.x, h0, l0); split2f(v.y, h1, l1);
    split2f(v.z, h2, l2); split2f(v.w, h3, l3);
    __half2* hp = (__half2*)hi;
    __half2* lp = (__half2*)lo;
    hp[2 * i]     = __half2{h0, h1};
    hp[2 * i + 1] = __half2{h2, h3};
    lp[2 * i]     = __half2{l0, l1};
    lp[2 * i + 1] = __half2{l2, l3};
}

__global__ __launch_bounds__(256) void cvt_f16(const float* __restrict__ src,
                                               f16* __restrict__ dst)
{
    size_t i = (size_t)blockIdx.x * 256 + threadIdx.x;
    float4 v = ((const float4*)src)[i];
    __half2* dp = (__half2*)dst;
    dp[2 * i]     = __floats2half2_rn(v.x, v.y);
    dp[2 * i + 1] = __floats2half2_rn(v.z, v.w);
}

// V transpose to single f16: g_v[(b*S+s), c] -> vT[(b*C+c), s]
__global__ __launch_bounds__(256) void transpose_v_f16()
{
    __shared__ float t[32][33];
    int b = blockIdx.z;
    int s0 = blockIdx.x * 32, c0 = blockIdx.y * 32;
    int tx = threadIdx.x, ty = threadIdx.y;  // 32 x 8
    #pragma unroll
    for (int j = 0; j < 4; j++) {
        int s = s0 + ty + j * 8;
        t[ty + j * 8][tx] = g_v[((size_t)b * NS + s) * NC + c0 + tx];
    }
    __syncthreads();
    #pragma unroll
    for (int j = 0; j < 4; j++) {
        int c = c0 + ty + j * 8;
        g_vtf[((size_t)b * NC + c) * NS + s0 + tx] = __float2half_rn(t[tx][ty + j * 8]);
    }
}

// Per-head RMSNorm + RoPE; reads fp32 g_q/g_k; writes Q split 2xf16, K single f16.
__global__ __launch_bounds__(256) void rmsnorm_rope(
    const float* __restrict__ rope,
    const float* __restrict__ gq, const float* __restrict__ gk)
{
    int warp = blockIdx.x * 8 + (threadIdx.x >> 5);
    int lane = threadIdx.x & 31;
    int m = warp >> 4;
    int h = warp & 15;
    int s = m & (NS - 1);

    size_t off = (size_t)m * NC + h * ND;
    const float* qr = g_q + off;
    const float* kr = g_k + off;
    const float* rp = rope + (size_t)s * (ND / 2) * 4;
    int d = lane * 4;

    float4 xq = *(const float4*)(qr + d);
    float4 xk = *(const float4*)(kr + d);
    float ssq = xq.x * xq.x + xq.y * xq.y + xq.z * xq.z + xq.w * xq.w;
    float ssk = xk.x * xk.x + xk.y * xk.y + xk.z * xk.z + xk.w * xk.w;
    #pragma unroll
    for (int o = 16; o; o >>= 1) {
        ssq += __shfl_xor_sync(0xffffffffu, ssq, o);
        ssk += __shfl_xor_sync(0xffffffffu, ssk, o);
    }
    float rq = rsqrtf(ssq * (1.0f / ND) + RMS_EPS);
    float rk = rsqrtf(ssk * (1.0f / ND) + RMS_EPS);

    float4 gqv = *(const float4*)(gq + d);
    float4 gkv = *(const float4*)(gk + d);
    xq.x *= rq * gqv.x; xq.y *= rq * gqv.y; xq.z *= rq * gqv.z; xq.w *= rq * gqv.w;
    xk.x *= rk * gkv.x; xk.y *= rk * gkv.y; xk.z *= rk * gkv.z; xk.w *= rk * gkv.w;

    float4 r0 = *(const float4*)(rp + (size_t)(2 * lane) * 4);
    float4 r1 = *(const float4*)(rp + (size_t)(2 * lane + 1) * 4);
    float4 oq, ok;
    oq.x = r0.x * xq.x + r0.y * xq.y;  oq.y = r0.z * xq.x + r0.w * xq.y;
    oq.z = r1.x * xq.z + r1.y * xq.w;  oq.w = r1.z * xq.z + r1.w * xq.w;
    ok.x = r0.x * xk.x + r0.y * xk.y;  ok.y = r0.z * xk.x + r0.w * xk.y;
    ok.z = r1.x * xk.z + r1.y * xk.w;  ok.w = r1.z * xk.z + r1.w * xk.w;

    f16 h0, h1, h2, h3, l0, l1, l2, l3;
    split2f(oq.x, h0, l0); split2f(oq.y, h1, l1);
    split2f(oq.z, h2, l2); split2f(oq.w, h3, l3);
    *(__half2*)(g_qhf + off + d)     = __half2{h0, h1};
    *(__half2*)(g_qhf + off + d + 2) = __half2{h2, h3};
    *(__half2*)(g_qlf + off + d)     = __half2{l0, l1};
    *(__half2*)(g_qlf + off + d + 2) = __half2{l2, l3};

    *(__half2*)(g_kf + off + d)     = __floats2half2_rn(ok.x, ok.y);
    *(__half2*)(g_kf + off + d + 2) = __floats2half2_rn(ok.z, ok.w);
}

// ---------------- launch ----------------
extern "C" void kernel_launch(void* const* d_in, const int* in_sizes, int n_in,
                              void* d_out, int out_size)
{
    const float* x    = (const float*)d_in[0];
    const float* rope = (const float*)d_in[1];
    const float* Wq   = (const float*)d_in[2];
    const float* bq   = (const float*)d_in[3];
    const float* Wk   = (const float*)d_in[4];
    const float* bk   = (const float*)d_in[5];
    const float* Wv   = (const float*)d_in[6];
    const float* bv   = (const float*)d_in[7];
    const float* gq   = (const float*)d_in[8];
    const float* gk   = (const float*)d_in[9];
    const float* Wo   = (const float*)d_in[10];
    const float* bo   = (const float*)d_in[11];
    float* out = (float*)d_out;

    cudaFuncSetAttribute(k_gemm_nt_f16, cudaFuncAttributeMaxDynamicSharedMemorySize, F16_SMEM);
    cudaFuncSetAttribute(k_flash, cudaFuncAttributeMaxDynamicSharedMemorySize, FLASH_SMEM);

    float *qp, *kp, *vp;
    f16 *xhf, *xlf, *wqf, *wkf, *wvf, *wof, *chf, *clf;
    cudaGetSymbolAddress((void**)&qp, g_q);
    cudaGetSymbolAddress((void**)&kp, g_k);
    cudaGetSymbolAddress((void**)&vp, g_v);
    cudaGetSymbolAddress((void**)&xhf, g_xhf); cudaGetSymbolAddress((void**)&xlf, g_xlf);
    cudaGetSymbolAddress((void**)&wqf, g_wqf); cudaGetSymbolAddress((void**)&wkf, g_wkf);
    cudaGetSymbolAddress((void**)&wvf, g_wvf); cudaGetSymbolAddress((void**)&wof, g_wof);
    cudaGetSymbolAddress((void**)&chf, g_chf); cudaGetSymbolAddress((void**)&clf, g_clf);

    const size_t nX = (size_t)NM * NC;       // 8M elems
    const size_t nW = (size_t)NC * NC;       // 4M elems

    cvt_split_f16<<<(unsigned)(nX / 1024), 256>>>(x, xhf, xlf);
    cvt_f16<<<(unsigned)(nW / 1024), 256>>>(Wq, wqf);
    cvt_f16<<<(unsigned)(nW / 1024), 256>>>(Wk, wkf);
    cvt_f16<<<(unsigned)(nW / 1024), 256>>>(Wv, wvf);
    cvt_f16<<<(unsigned)(nW / 1024), 256>>>(Wo, wof);

    dim3 gProj(NC / 128, NM / 128);          // (16, 32)
    k_gemm_nt_f16<<<gProj, 256, F16_SMEM>>>(xhf, xlf, wqf, bq, qp);
    k_gemm_nt_f16<<<gProj, 256, F16_SMEM>>>(xhf, xlf, wkf, bk, kp);
    k_gemm_nt_f16<<<gProj, 256, F16_SMEM>>>(xhf, xlf, wvf, bv, vp);

    rmsnorm_rope<<<(NM * NH) / 8, 256>>>(rope, gq, gk);
    transpose_v_f16<<<dim3(NS / 32, NC / 32, NB), dim3(32, 8)>>>();

    k_flash<<<dim3(NS / 128, NBH), 256, FLASH_SMEM>>>();

    k_gemm_nt_f16<<<gProj, 256, F16_SMEM>>>(chf, clf, wof, bo, out);
}

// round 11
// speedup vs baseline: 3.3550x; 1.0139x over previous
#include <cuda_runtime.h>
#include <cuda_bf16.h>
#include <cuda_fp16.h>
#include <math.h>
#include <stdint.h>
#include <stddef.h>

#define NB 2
#define NS 2048
#define NC 2048
#define ND 128
#define NH 16
#define NM (NB * NS)       // 4096
#define NBH (NB * NH)      // 32
#define RMS_EPS 1.1920928955078125e-07f
#define SM_SCALE 0.08838834764831844f

typedef __half f16;

// ---------------- scratch (device globals; no allocation) ----------------
__device__ float g_q[(size_t)NM * NC];
__device__ float g_k[(size_t)NM * NC];
__device__ float g_v[(size_t)NM * NC];

// f16 operands
__device__ f16 g_xhf[(size_t)NM * NC], g_xlf[(size_t)NM * NC];
__device__ f16 g_wqf[(size_t)NC * NC], g_wkf[(size_t)NC * NC];
__device__ f16 g_wvf[(size_t)NC * NC], g_wof[(size_t)NC * NC];
__device__ f16 g_vtf[(size_t)NB * NC * NS];
__device__ f16 g_chf[(size_t)NM * NC], g_clf[(size_t)NM * NC];
__device__ f16 g_qhf[(size_t)NM * NC], g_qlf[(size_t)NM * NC];   // Q split 2xf16
__device__ f16 g_kf[(size_t)NM * NC];                            // K single f16

// ---------------- PTX helpers (sm_80-era, family-target safe) -------------
__device__ __forceinline__ uint32_t smem_to_u32(const void* p) {
    uint32_t a;
    asm("{ .reg .u64 t; cvta.to.shared.u64 t, %1; cvt.u32.u64 %0, t; }"
        : "=r"(a) : "l"(p));
    return a;
}
__device__ __forceinline__ void cp_async16(uint32_t dst, const void* src) {
    asm volatile("cp.async.cg.shared.global [%0], [%1], 16;"
                 :: "r"(dst), "l"(src) : "memory");
}
__device__ __forceinline__ void cp_commit() {
    asm volatile("cp.async.commit_group;" ::: "memory");
}
template <int N>
__device__ __forceinline__ void cp_wait() {
    asm volatile("cp.async.wait_group %0;" :: "n"(N) : "memory");
}
__device__ __forceinline__ void ldm_x4(uint32_t (&r)[4], uint32_t addr) {
    asm volatile("ldmatrix.sync.aligned.m8n8.x4.shared.b16 {%0,%1,%2,%3}, [%4];"
                 : "=r"(r[0]), "=r"(r[1]), "=r"(r[2]), "=r"(r[3]) : "r"(addr));
}
__device__ __forceinline__ void mma_f16(float (&d)[4], const uint32_t (&a)[4],
                                        uint32_t b0, uint32_t b1) {
    asm volatile("mma.sync.aligned.m16n8k16.row.col.f32.f16.f16.f32 "
                 "{%0,%1,%2,%3}, {%4,%5,%6,%7}, {%8,%9}, {%0,%1,%2,%3};"
                 : "+f"(d[0]), "+f"(d[1]), "+f"(d[2]), "+f"(d[3])
                 : "r"(a[0]), "r"(a[1]), "r"(a[2]), "r"(a[3]), "r"(b0), "r"(b1));
}

__device__ __forceinline__ void split2f(float x, f16& h, f16& l) {
    h = __float2half_rn(x);
    l = __float2half_rn(x - __half2float(h));
}
__device__ __forceinline__ uint32_t pack_f16x2(float x, float y) {
    __half2 H = __floats2half2_rn(x, y);
    return *reinterpret_cast<uint32_t*>(&H);
}

// ---------------- common tiling constants ----------------
#define KCH 32
#define ROW_BYTES 80
#define TILE_BYTES (128 * ROW_BYTES)        // 10240

__device__ __forceinline__ void load_tile_async(uint32_t smbase, const void* g,
                                                int ld, int k0, int tid) {
    const char* gp = (const char*)g + (size_t)k0 * 2;
    #pragma unroll
    for (int j = 0; j < 2; j++) {
        int i = tid + j * 256;
        int row = i >> 2;
        int c = i & 3;
        cp_async16(smbase + row * ROW_BYTES + c * 16,
                   gp + (size_t)row * ld * 2 + c * 16);
    }
}

// =========================================================================
// f16 2-term GEMM (QKV + out-proj): A split 2xf16, B single f16.
// 3-stage cp.async pipeline: 2 chunks always in flight.
// =========================================================================
#define F16_STAGE (3 * TILE_BYTES)          // 30720
#define F16_SMEM (3 * F16_STAGE)            // 92160

__global__ __launch_bounds__(256)
void k_gemm_nt_f16(const f16* __restrict__ AhG, const f16* __restrict__ AlG,
                   const f16* __restrict__ BfG, const float* __restrict__ biasG,
                   float* __restrict__ OutG)
{
    size_t bm = (size_t)blockIdx.y * 128;
    size_t bn = (size_t)blockIdx.x * 128;
    const f16* Ah = AhG + bm * NC;
    const f16* Al = AlG + bm * NC;
    const f16* Bf = BfG + bn * NC;
    const float* bias = biasG + bn;
    float* Out = OutG + bm * NC + bn;

    extern __shared__ char sm[];
    uint32_t sb = smem_to_u32(sm);
    const int tid = threadIdx.x;
    const int lane = tid & 31;
    const int warp = tid >> 5;
    const int wm = warp >> 1;
    const int wn = warp & 1;

    float acc[2][8][4];
    #pragma unroll
    for (int mt = 0; mt < 2; mt++)
        #pragma unroll
        for (int nt = 0; nt < 8; nt++)
            #pragma unroll
            for (int j = 0; j < 4; j++) acc[mt][nt][j] = 0.0f;

    const int nch = NC / KCH;

    auto load_chunk = [&](int ch, int s) {
        uint32_t base = sb + s * F16_STAGE;
        int k0 = ch * KCH;
        load_tile_async(base,                  Ah, NC, k0, tid);
        load_tile_async(base + TILE_BYTES,     Al, NC, k0, tid);
        load_tile_async(base + 2 * TILE_BYTES, Bf, NC, k0, tid);
    };

    load_chunk(0, 0);
    cp_commit();
    load_chunk(1, 1);
    cp_commit();

    int stage = 0;
    for (int ch = 0; ch < nch; ch++) {
        if (ch + 1 < nch) cp_wait<1>(); else cp_wait<0>();
        __syncthreads();
        if (ch + 2 < nch) {
            int ns = stage + 2;
            if (ns >= 3) ns -= 3;
            load_chunk(ch + 2, ns);
            cp_commit();
        }

        uint32_t base = sb + stage * F16_STAGE;
        if (++stage == 3) stage = 0;

        #pragma unroll
        for (int ks = 0; ks < 2; ks++) {
            uint32_t koff = (uint32_t)(ks * 32 + (lane >> 4) * 16);
            uint32_t ah[2][4], al[2][4];
            #pragma unroll
            for (int mt = 0; mt < 2; mt++) {
                uint32_t r = wm * 32 + mt * 16 + (lane & 15);
                uint32_t addr = base + r * ROW_BYTES + koff;
                ldm_x4(ah[mt], addr);
                ldm_x4(al[mt], addr + TILE_BYTES);
            }
            uint32_t bfr[4][4];
            #pragma unroll
            for (int ng = 0; ng < 4; ng++) {
                uint32_t r = wn * 64 + ng * 16 + (lane & 15);
                ldm_x4(bfr[ng], base + 2 * TILE_BYTES + r * ROW_BYTES + koff);
            }
            #pragma unroll
            for (int mt = 0; mt < 2; mt++)
                #pragma unroll
                for (int ng = 0; ng < 4; ng++) {
                    mma_f16(acc[mt][2 * ng],     ah[mt], bfr[ng][0], bfr[ng][2]);
                    mma_f16(acc[mt][2 * ng],     al[mt], bfr[ng][0], bfr[ng][2]);
                    mma_f16(acc[mt][2 * ng + 1], ah[mt], bfr[ng][1], bfr[ng][3]);
                    mma_f16(acc[mt][2 * ng + 1], al[mt], bfr[ng][1], bfr[ng][3]);
                }
        }
    }

    #pragma unroll
    for (int mt = 0; mt < 2; mt++) {
        int r0 = wm * 32 + mt * 16 + (lane >> 2);
        #pragma unroll
        for (int nt = 0; nt < 8; nt++) {
            int c = wn * 64 + nt * 8 + (lane & 3) * 2;
            float bx = bias[c], by = bias[c + 1];
            float2 v0 = { acc[mt][nt][0] + bx, acc[mt][nt][1] + by };
            float2 v1 = { acc[mt][nt][2] + bx, acc[mt][nt][3] + by };
            *(float2*)(Out + (size_t)r0 * NC + c) = v0;
            *(float2*)(Out + (size_t)(r0 + 8) * NC + c) = v1;
        }
    }
}

// =========================================================================
// Flash attention: scores (f16 2-term) + online softmax + PV (f16 1-term)
// Double-buffered K AND V: one wait + two barriers per iteration.
// smem layout: [K0 | K1 | V0 | V1], K_j / V_j live in buffer (j+1)&1.
// =========================================================================
#define FT_ROWB 272                          // 256B row + 16B pad
#define FT_TILE (128 * FT_ROWB)              // 34816
#define OFF_K 0
#define OFF_V (2 * FT_TILE)
#define FLASH_SMEM (4 * FT_TILE)             // 139264

__device__ __forceinline__ void fa_load_one(uint32_t dst, const f16* g,
                                            size_t rowbase, size_t ldrow, int tid)
{
    #pragma unroll
    for (int i = 0; i < 8; i++) {
        int idx = tid + i * 256;
        int row = idx >> 4;
        int ch = idx & 15;
        cp_async16(dst + row * FT_ROWB + ch * 16,
                   (const char*)(g + rowbase + (size_t)row * ldrow) + ch * 16);
    }
}

__global__ void __launch_bounds__(256, 1) k_flash()
{
    extern __shared__ char sm[];
    uint32_t sb = smem_to_u32(sm);
    const int tid = threadIdx.x;
    const int lane = tid & 31;
    const int warp = tid >> 5;
    const int q0 = blockIdx.x * 128;
    const int bh = blockIdx.y, b = bh >> 4, h = bh & 15;

    const size_t kbase = (size_t)(b * NS) * NC + (size_t)h * ND;
    const size_t vbase = ((size_t)b * NC + (size_t)h * ND) * NS;

    // ---- stage Q hi/lo through buffers K0/V0; K0&V0 data go to buffer 1 ----
    size_t qbase = (size_t)(b * NS + q0) * NC + (size_t)h * ND;
    fa_load_one(sb + OFF_K, g_qhf, qbase, NC, tid);
    fa_load_one(sb + OFF_V, g_qlf, qbase, NC, tid);
    cp_commit();                                        // group: Q
    fa_load_one(sb + OFF_K + FT_TILE, g_kf, kbase, NC, tid);
    fa_load_one(sb + OFF_V + FT_TILE, g_vtf, vbase, NS, tid);
    cp_commit();                                        // group: K0,V0
    cp_wait<1>();                                       // Q ready
    __syncthreads();

    uint32_t qhf[8][4], qlf[8][4];
    {
        uint32_t rbase = sb + (warp * 16 + (lane & 15)) * FT_ROWB + ((lane >> 4) << 4);
        #pragma unroll
        for (int ks = 0; ks < 8; ks++) {
            ldm_x4(qhf[ks], rbase + OFF_K + ks * 32);
            ldm_x4(qlf[ks], rbase + OFF_V + ks * 32);
        }
    }
    __syncthreads();                                    // Q buffers free

    fa_load_one(sb + OFF_K, g_kf, kbase + (size_t)128 * NC, NC, tid);
    fa_load_one(sb + OFF_V, g_vtf, vbase + 128, NS, tid);
    cp_commit();                                        // group: K1,V1

    float o[16][4];
    #pragma unroll
    for (int i = 0; i < 16; i++) { o[i][0] = 0.f; o[i][1] = 0.f; o[i][2] = 0.f; o[i][3] = 0.f; }
    float m0 = -1e30f, m1 = -1e30f, l0 = 0.f, l1 = 0.f;

    for (int j = 0; j < 16; j++) {
        // groups pending: {KV_j, KV_{j+1}} -> wait for KV_j
        if (j + 1 < 16) cp_wait<1>(); else cp_wait<0>();
        __syncthreads();

        uint32_t bufo = (uint32_t)((j + 1) & 1) * FT_TILE;

        // (B) S = Q @ K_j^T  (f16 2-term)
        float s[16][4];
        #pragma unroll
        for (int i = 0; i < 16; i++) { s[i][0] = 0.f; s[i][1] = 0.f; s[i][2] = 0.f; s[i][3] = 0.f; }
        #pragma unroll
        for (int ng = 0; ng < 8; ng++) {
            #pragma unroll
            for (int ks = 0; ks < 8; ks++) {
                uint32_t addr = sb + OFF_K + bufo + (ng * 16 + (lane & 15)) * FT_ROWB
                              + ((lane >> 4) << 4) + ks * 32;
                uint32_t kf4[4];
                ldm_x4(kf4, addr);
                mma_f16(s[2 * ng],     qhf[ks], kf4[0], kf4[2]);
                mma_f16(s[2 * ng],     qlf[ks], kf4[0], kf4[2]);
                mma_f16(s[2 * ng + 1], qhf[ks], kf4[1], kf4[3]);
                mma_f16(s[2 * ng + 1], qlf[ks], kf4[1], kf4[3]);
            }
        }

        // (D) online softmax: p = exp((s - m)*scale) <= 1 (f16-safe by construction)
        float mx0 = -1e30f, mx1 = -1e30f;
        #pragma unroll
        for (int i = 0; i < 16; i++) {
            mx0 = fmaxf(mx0, fmaxf(s[i][0], s[i][1]));
            mx1 = fmaxf(mx1, fmaxf(s[i][2], s[i][3]));
        }
        mx0 = fmaxf(mx0, __shfl_xor_sync(0xffffffffu, mx0, 1));
        mx0 = fmaxf(mx0, __shfl_xor_sync(0xffffffffu, mx0, 2));
        mx1 = fmaxf(mx1, __shfl_xor_sync(0xffffffffu, mx1, 1));
        mx1 = fmaxf(mx1, __shfl_xor_sync(0xffffffffu, mx1, 2));
        float nm0 = fmaxf(m0, mx0), nm1 = fmaxf(m1, mx1);
        float a0 = __expf((m0 - nm0) * SM_SCALE);
        float a1 = __expf((m1 - nm1) * SM_SCALE);
        m0 = nm0; m1 = nm1;
        float ps0 = 0.f, ps1 = 0.f;
        #pragma unroll
        for (int i = 0; i < 16; i++) {
            s[i][0] = __expf((s[i][0] - m0) * SM_SCALE);
            s[i][1] = __expf((s[i][1] - m0) * SM_SCALE);
            s[i][2] = __expf((s[i][2] - m1) * SM_SCALE);
            s[i][3] = __expf((s[i][3] - m1) * SM_SCALE);
            ps0 += s[i][0] + s[i][1];
            ps1 += s[i][2] + s[i][3];
        }
        l0 = l0 * a0 + ps0;
        l1 = l1 * a1 + ps1;
        #pragma unroll
        for (int i = 0; i < 16; i++) {
            o[i][0] *= a0; o[i][1] *= a0; o[i][2] *= a1; o[i][3] *= a1;
        }

        // (F) ctx += P @ V_j  (P single f16 in [0,1], V single f16)
        #pragma unroll
        for (int ks = 0; ks < 8; ks++) {
            uint32_t pa[4];
            pa[0] = pack_f16x2(s[2 * ks][0],     s[2 * ks][1]);
            pa[1] = pack_f16x2(s[2 * ks][2],     s[2 * ks][3]);
            pa[2] = pack_f16x2(s[2 * ks + 1][0], s[2 * ks + 1][1]);
            pa[3] = pack_f16x2(s[2 * ks + 1][2], s[2 * ks + 1][3]);
            #pragma unroll
            for (int ng = 0; ng < 8; ng++) {
                uint32_t addr = sb + OFF_V + bufo + (ng * 16 + (lane & 15)) * FT_ROWB
                              + ((lane >> 4) << 4) + ks * 32;
                uint32_t vf4[4];
                ldm_x4(vf4, addr);
                mma_f16(o[2 * ng],     pa, vf4[0], vf4[2]);
                mma_f16(o[2 * ng + 1], pa, vf4[1], vf4[3]);
            }
        }

        // (G) buffers for iter j are free -> start K_{j+2}, V_{j+2} into them
        __syncthreads();
        if (j + 2 < 16) {
            fa_load_one(sb + OFF_K + bufo, g_kf,
                        kbase + (size_t)(j + 2) * 128 * NC, NC, tid);
            fa_load_one(sb + OFF_V + bufo, g_vtf,
                        vbase + (size_t)(j + 2) * 128, NS, tid);
            cp_commit();
        }
    }

    // ---- finalize: normalize, split to f16 hi/lo, write ctx ----
    l0 += __shfl_xor_sync(0xffffffffu, l0, 1);
    l0 += __shfl_xor_sync(0xffffffffu, l0, 2);
    l1 += __shfl_xor_sync(0xffffffffu, l1, 1);
    l1 += __shfl_xor_sync(0xffffffffu, l1, 2);
    float i0 = 1.0f / l0, i1 = 1.0f / l1;

    size_t gr0 = (size_t)(b * NS + q0 + warp * 16 + (lane >> 2));
    #pragma unroll
    for (int nt = 0; nt < 16; nt++) {
        int c = h * ND + nt * 8 + (lane & 3) * 2;
        f16 h0, h1, lo0, lo1;
        split2f(o[nt][0] * i0, h0, lo0);
        split2f(o[nt][1] * i0, h1, lo1);
        *(__half2*)(g_chf + gr0 * NC + c) = __half2{h0, h1};
        *(__half2*)(g_clf + gr0 * NC + c) = __half2{lo0, lo1};
        split2f(o[nt][2] * i1, h0, lo0);
        split2f(o[nt][3] * i1, h1, lo1);
        *(__half2*)(g_chf + (gr0 + 8) * NC + c) = __half2{h0, h1};
        *(__half2*)(g_clf + (gr0 + 8) * NC + c) = __half2{lo0, lo1};
    }
}

// ---------------- elementwise kernels ----------------
__global__ __launch_bounds__(256) void cvt_split_f16(const float* __restrict__ src,
                                                     f16* __restrict__ hi,
                                                     f16* __restrict__ lo)
{
    size_t i = (size_t)blockIdx.x * 256 + threadIdx.x;
    float4 v = ((const float4*)src)[i];
    f16 h0, h1, h2, h3, l0, l1, l2, l3;
    split2f(v.x, h0, l0); split2f(v.y, h1, l1);
    split2f(v.z, h2, l2); split2f(v.w, h3, l3);
    __half2* hp = (__half2*)hi;
    __half2* lp = (__half2*)lo;
    hp[2 * i]     = __half2{h0, h1};
    hp[2 * i + 1] = __half2{h2, h3};
    lp[2 * i]     = __half2{l0, l1};
    lp[2 * i + 1] = __half2{l2, l3};
}

// Convert the 4 weight matrices in one launch: blockIdx.y selects tensor.
__global__ __launch_bounds__(256) void cvt_f16_w(
    const float* __restrict__ s0, const float* __restrict__ s1,
    const float* __restrict__ s2, const float* __restrict__ s3,
    f16* __restrict__ d0, f16* __restrict__ d1,
    f16* __restrict__ d2, f16* __restrict__ d3)
{
    const float* src = (blockIdx.y == 0) ? s0 : (blockIdx.y == 1) ? s1
                     : (blockIdx.y == 2) ? s2 : s3;
    f16* dst = (blockIdx.y == 0) ? d0 : (blockIdx.y == 1) ? d1
             : (blockIdx.y == 2) ? d2 : d3;
    size_t i = (size_t)blockIdx.x * 256 + threadIdx.x;
    float4 v = ((const float4*)src)[i];
    __half2* dp = (__half2*)dst;
    dp[2 * i]     = __floats2half2_rn(v.x, v.y);
    dp[2 * i + 1] = __floats2half2_rn(v.z, v.w);
}

// V transpose to single f16: g_v[(b*S+s), c] -> vT[(b*C+c), s]
__global__ __launch_bounds__(256) void transpose_v_f16()
{
    __shared__ float t[32][33];
    int b = blockIdx.z;
    int s0 = blockIdx.x * 32, c0 = blockIdx.y * 32;
    int tx = threadIdx.x, ty = threadIdx.y;  // 32 x 8
    #pragma unroll
    for (int j = 0; j < 4; j++) {
        int s = s0 + ty + j * 8;
        t[ty + j * 8][tx] = g_v[((size_t)b * NS + s) * NC + c0 + tx];
    }
    __syncthreads();
    #pragma unroll
    for (int j = 0; j < 4; j++) {
        int c = c0 + ty + j * 8;
        g_vtf[((size_t)b * NC + c) * NS + s0 + tx] = __float2half_rn(t[tx][ty + j * 8]);
    }
}

// Per-head RMSNorm + RoPE; reads fp32 g_q/g_k; writes Q split 2xf16, K single f16.
__global__ __launch_bounds__(256) void rmsnorm_rope(
    const float* __restrict__ rope,
    const float* __restrict__ gq, const float* __restrict__ gk)
{
    int warp = blockIdx.x * 8 + (threadIdx.x >> 5);
    int lane = threadIdx.x & 31;
    int m = warp >> 4;
    int h = warp & 15;
    int s = m & (NS - 1);

    size_t off = (size_t)m * NC + h * ND;
    const float* qr = g_q + off;
    const float* kr = g_k + off;
    const float* rp = rope + (size_t)s * (ND / 2) * 4;
    int d = lane * 4;

    float4 xq = *(const float4*)(qr + d);
    float4 xk = *(const float4*)(kr + d);
    float ssq = xq.x * xq.x + xq.y * xq.y + xq.z * xq.z + xq.w * xq.w;
    float ssk = xk.x * xk.x + xk.y * xk.y + xk.z * xk.z + xk.w * xk.w;
    #pragma unroll
    for (int o = 16; o; o >>= 1) {
        ssq += __shfl_xor_sync(0xffffffffu, ssq, o);
        ssk += __shfl_xor_sync(0xffffffffu, ssk, o);
    }
    float rq = rsqrtf(ssq * (1.0f / ND) + RMS_EPS);
    float rk = rsqrtf(ssk * (1.0f / ND) + RMS_EPS);

    float4 gqv = *(const float4*)(gq + d);
    float4 gkv = *(const float4*)(gk + d);
    xq.x *= rq * gqv.x; xq.y *= rq * gqv.y; xq.z *= rq * gqv.z; xq.w *= rq * gqv.w;
    xk.x *= rk * gkv.x; xk.y *= rk * gkv.y; xk.z *= rk * gkv.z; xk.w *= rk * gkv.w;

    float4 r0 = *(const float4*)(rp + (size_t)(2 * lane) * 4);
    float4 r1 = *(const float4*)(rp + (size_t)(2 * lane + 1) * 4);
    float4 oq, ok;
    oq.x = r0.x * xq.x + r0.y * xq.y;  oq.y = r0.z * xq.x + r0.w * xq.y;
    oq.z = r1.x * xq.z + r1.y * xq.w;  oq.w = r1.z * xq.z + r1.w * xq.w;
    ok.x = r0.x * xk.x + r0.y * xk.y;  ok.y = r0.z * xk.x + r0.w * xk.y;
    ok.z = r1.x * xk.z + r1.y * xk.w;  ok.w = r1.z * xk.z + r1.w * xk.w;

    f16 h0, h1, h2, h3, l0, l1, l2, l3;
    split2f(oq.x, h0, l0); split2f(oq.y, h1, l1);
    split2f(oq.z, h2, l2); split2f(oq.w, h3, l3);
    *(__half2*)(g_qhf + off + d)     = __half2{h0, h1};
    *(__half2*)(g_qhf + off + d + 2) = __half2{h2, h3};
    *(__half2*)(g_qlf + off + d)     = __half2{l0, l1};
    *(__half2*)(g_qlf + off + d + 2) = __half2{l2, l3};

    *(__half2*)(g_kf + off + d)     = __floats2half2_rn(ok.x, ok.y);
    *(__half2*)(g_kf + off + d + 2) = __floats2half2_rn(ok.z, ok.w);
}

// ---------------- launch ----------------
extern "C" void kernel_launch(void* const* d_in, const int* in_sizes, int n_in,
                              void* d_out, int out_size)
{
    const float* x    = (const float*)d_in[0];
    const float* rope = (const float*)d_in[1];
    const float* Wq   = (const float*)d_in[2];
    const float* bq   = (const float*)d_in[3];
    const float* Wk   = (const float*)d_in[4];
    const float* bk   = (const float*)d_in[5];
    const float* Wv   = (const float*)d_in[6];
    const float* bv   = (const float*)d_in[7];
    const float* gq   = (const float*)d_in[8];
    const float* gk   = (const float*)d_in[9];
    const float* Wo   = (const float*)d_in[10];
    const float* bo   = (const float*)d_in[11];
    float* out = (float*)d_out;

    cudaFuncSetAttribute(k_gemm_nt_f16, cudaFuncAttributeMaxDynamicSharedMemorySize, F16_SMEM);
    cudaFuncSetAttribute(k_flash, cudaFuncAttributeMaxDynamicSharedMemorySize, FLASH_SMEM);

    float *qp, *kp, *vp;
    f16 *xhf, *xlf, *wqf, *wkf, *wvf, *wof, *chf, *clf;
    cudaGetSymbolAddress((void**)&qp, g_q);
    cudaGetSymbolAddress((void**)&kp, g_k);
    cudaGetSymbolAddress((void**)&vp, g_v);
    cudaGetSymbolAddress((void**)&xhf, g_xhf); cudaGetSymbolAddress((void**)&xlf, g_xlf);
    cudaGetSymbolAddress((void**)&wqf, g_wqf); cudaGetSymbolAddress((void**)&wkf, g_wkf);
    cudaGetSymbolAddress((void**)&wvf, g_wvf); cudaGetSymbolAddress((void**)&wof, g_wof);
    cudaGetSymbolAddress((void**)&chf, g_chf); cudaGetSymbolAddress((void**)&clf, g_clf);

    const size_t nX = (size_t)NM * NC;       // 8M elems
    const size_t nW = (size_t)NC * NC;       // 4M elems

    cvt_split_f16<<<(unsigned)(nX / 1024), 256>>>(x, xhf, xlf);
    cvt_f16_w<<<dim3((unsigned)(nW / 1024), 4), 256>>>(Wq, Wk, Wv, Wo,
                                                       wqf, wkf, wvf, wof);

    dim3 gProj(NC / 128, NM / 128);          // (16, 32)
    k_gemm_nt_f16<<<gProj, 256, F16_SMEM>>>(xhf, xlf, wqf, bq, qp);
    k_gemm_nt_f16<<<gProj, 256, F16_SMEM>>>(xhf, xlf, wkf, bk, kp);
    k_gemm_nt_f16<<<gProj, 256, F16_SMEM>>>(xhf, xlf, wvf, bv, vp);

    rmsnorm_rope<<<(NM * NH) / 8, 256>>>(rope, gq, gk);
    transpose_v_f16<<<dim3(NS / 32, NC / 32, NB), dim3(32, 8)>>>();

    k_flash<<<dim3(NS / 128, NBH), 256, FLASH_SMEM>>>();

    k_gemm_nt_f16<<<gProj, 256, F16_SMEM>>>(chf, clf, wof, bo, out);
}